// round 3
// baseline (speedup 1.0000x reference)
#include <cuda_runtime.h>

// Problem constants (fixed by the dataset shapes)
#define B_  8
#define T_  4096
#define D_  1024
#define H_  16
#define DH_ 64
#define UMAX 44   // actual u = 41; small headroom

// ---------------- scratch (device globals; no runtime allocation) ----------------
__device__ float g_Xs [B_*UMAX*D_];          // gathered x rows       (1.4 MB)
__device__ float g_Qs [B_*UMAX*D_];          // Q at idx              (1.4 MB)
__device__ float g_Qt [B_*H_*UMAX*D_];       // (Qs_h @ Wk_h)*scale   (23 MB)
__device__ float g_S  [(long)B_*H_*UMAX*T_]; // scores/attn           (92 MB)
__device__ float g_AX [B_*H_*UMAX*D_];       // attn @ x              (23 MB)
__device__ float g_ctx[B_*H_*UMAX*DH_];      // context               (1.4 MB)
__device__ float g_mn [B_*H_*DH_];           // mean ctx
__device__ float g_Y  [B_*(UMAX+1)*D_];      // assembled rows
__device__ float g_O  [B_*(UMAX+1)*D_];      // rows after Wo

// ---------------- generic SGEMM: 128x128 tile, BK=8, 256 thr, 8x8 microtile ----
// NT: C[m,n] = sum_k A[m,k]*B[n,k]   (both row-major, K contiguous)
// NN: C[m,n] = sum_k A[m,k]*B[k,n]   (B row-major KxN)
template<bool NT>
__global__ void __launch_bounds__(256, 2)
sgemm(const float* __restrict__ Ag, const float* __restrict__ Bg,
      float* __restrict__ Cg, int M, int N, int K,
      long sA, long sB, long sC, const float* __restrict__ bias)
{
    const int bb = blockIdx.z;
    const float* A  = Ag + (long)bb * sA;
    const float* Bp = Bg + (long)bb * sB;
    float*       C  = Cg + (long)bb * sC;

    __shared__ float As[8][128];
    __shared__ float Bs[8][128];

    const int m0 = blockIdx.y * 128;
    const int n0 = blockIdx.x * 128;
    const int tid = threadIdx.x;

    const int arow = tid >> 1;         // 0..127
    const int ak4  = (tid & 1) * 4;    // 0 or 4
    const int bk   = tid >> 5;         // 0..7   (NN)
    const int bn4  = (tid & 31) * 4;   // 0..124 (NN)

    float acc[8][8];
    #pragma unroll
    for (int i = 0; i < 8; i++)
        #pragma unroll
        for (int j = 0; j < 8; j++) acc[i][j] = 0.f;

    const int tm = (tid >> 4) * 8;     // 8-aligned -> float4-safe smem reads
    const int tn = (tid & 15) * 8;

    for (int k0 = 0; k0 < K; k0 += 8) {
        // A tile -> As[k][m] (transposed so the inner loop reads m-contiguous)
        {
            int gm = m0 + arow;
            float4 v = make_float4(0.f, 0.f, 0.f, 0.f);
            if (gm < M) v = *reinterpret_cast<const float4*>(A + (long)gm * K + k0 + ak4);
            As[ak4 + 0][arow] = v.x; As[ak4 + 1][arow] = v.y;
            As[ak4 + 2][arow] = v.z; As[ak4 + 3][arow] = v.w;
        }
        if (NT) {
            int gn = n0 + arow;
            float4 v = make_float4(0.f, 0.f, 0.f, 0.f);
            if (gn < N) v = *reinterpret_cast<const float4*>(Bp + (long)gn * K + k0 + ak4);
            Bs[ak4 + 0][arow] = v.x; Bs[ak4 + 1][arow] = v.y;
            Bs[ak4 + 2][arow] = v.z; Bs[ak4 + 3][arow] = v.w;
        } else {
            float4 v = *reinterpret_cast<const float4*>(Bp + (long)(k0 + bk) * N + n0 + bn4);
            *reinterpret_cast<float4*>(&Bs[bk][bn4]) = v;
        }
        __syncthreads();

        #pragma unroll
        for (int kk = 0; kk < 8; kk++) {
            float ar[8], br[8];
            *reinterpret_cast<float4*>(&ar[0]) = *reinterpret_cast<const float4*>(&As[kk][tm]);
            *reinterpret_cast<float4*>(&ar[4]) = *reinterpret_cast<const float4*>(&As[kk][tm + 4]);
            *reinterpret_cast<float4*>(&br[0]) = *reinterpret_cast<const float4*>(&Bs[kk][tn]);
            *reinterpret_cast<float4*>(&br[4]) = *reinterpret_cast<const float4*>(&Bs[kk][tn + 4]);
            #pragma unroll
            for (int i = 0; i < 8; i++)
                #pragma unroll
                for (int j = 0; j < 8; j++) acc[i][j] += ar[i] * br[j];
        }
        __syncthreads();
    }

    #pragma unroll
    for (int i = 0; i < 8; i++) {
        int gm = m0 + tm + i;
        if (gm >= M) break;
        #pragma unroll
        for (int j = 0; j < 8; j++) {
            int gn = n0 + tn + j;
            float v = acc[i][j];
            if (bias) v += bias[gn];
            C[(long)gm * N + gn] = v;
        }
    }
}

// ---------------- gather x rows at idx -> g_Xs ----------------
__global__ void gather_kernel(const float* __restrict__ x, const int* __restrict__ idx, int u)
{
    int j = blockIdx.x, b = blockIdx.y;
    int t = idx[j];
    const float4* src = reinterpret_cast<const float4*>(x + ((long)b * T_ + t) * D_);
    float4* dst = reinterpret_cast<float4*>(g_Xs + ((long)b * u + j) * D_);
    dst[threadIdx.x] = src[threadIdx.x];   // 256 threads * float4 = 1024 floats
}

// ---------------- Qt[b, h*u+j, :] = scale * Qs[b,j,h*64:...] @ Wk_h ----------------
__global__ void qt_kernel(const float* __restrict__ Wk, int u)
{
    int j = blockIdx.x, h = blockIdx.y, b = blockIdx.z;
    __shared__ float q[DH_];
    int tid = threadIdx.x;   // 256
    if (tid < DH_) q[tid] = g_Qs[((long)b * u + j) * D_ + h * DH_ + tid];
    __syncthreads();

    const float* W = Wk + (long)h * DH_ * D_;
    float acc[4] = {0.f, 0.f, 0.f, 0.f};
    for (int c = 0; c < DH_; c++) {
        float qv = q[c];
        const float* wr = W + (long)c * D_;
        #pragma unroll
        for (int r = 0; r < 4; r++) acc[r] += qv * wr[tid + r * 256];
    }
    float* out = g_Qt + ((long)b * H_ * u + (long)h * u + j) * D_;
    const float scale = 0.125f;   // 1/sqrt(DH)
    #pragma unroll
    for (int r = 0; r < 4; r++) out[tid + r * 256] = acc[r] * scale;
}

// ---------------- row softmax over T (in place on g_S) ----------------
__global__ void softmax_kernel()
{
    long row = blockIdx.x;
    float* s = g_S + row * (long)T_;
    int tid = threadIdx.x;   // 256
    __shared__ float red[256];

    float mx = -1e30f;
    for (int t = tid; t < T_; t += 256) mx = fmaxf(mx, s[t]);
    red[tid] = mx; __syncthreads();
    for (int o = 128; o > 0; o >>= 1) { if (tid < o) red[tid] = fmaxf(red[tid], red[tid + o]); __syncthreads(); }
    mx = red[0]; __syncthreads();

    float sum = 0.f;
    for (int t = tid; t < T_; t += 256) { float e = __expf(s[t] - mx); s[t] = e; sum += e; }
    red[tid] = sum; __syncthreads();
    for (int o = 128; o > 0; o >>= 1) { if (tid < o) red[tid] += red[tid + o]; __syncthreads(); }
    float inv = 1.f / red[0];
    for (int t = tid; t < T_; t += 256) s[t] *= inv;
}

// ---------------- ctx[b,h,j,:] = AX[b,h*u+j,:] @ Wv_h^T ----------------
__global__ void ctx_kernel(const float* __restrict__ Wv, int u)
{
    int j = blockIdx.x, h = blockIdx.y, b = blockIdx.z;
    __shared__ float ax[D_];
    int tid = threadIdx.x;   // 64
    const float* AXrow = g_AX + ((long)b * H_ * u + (long)h * u + j) * D_;
    for (int i = tid; i < D_ / 4; i += 64)
        reinterpret_cast<float4*>(ax)[i] = reinterpret_cast<const float4*>(AXrow)[i];
    __syncthreads();

    const float* wr = Wv + (long)(h * DH_ + tid) * D_;
    float acc = 0.f;
    #pragma unroll 4
    for (int d4 = 0; d4 < D_ / 4; d4++) {
        float4 w = reinterpret_cast<const float4*>(wr)[d4];
        float4 a = reinterpret_cast<const float4*>(ax)[d4];
        acc += a.x * w.x + a.y * w.y + a.z * w.z + a.w * w.w;
    }
    g_ctx[((long)(b * H_ + h) * u + j) * DH_ + tid] = acc;
}

// ---------------- mean over u ----------------
__global__ void mean_kernel(int u)
{
    int h = blockIdx.x, b = blockIdx.y;
    int e = threadIdx.x;   // 64
    float s = 0.f;
    const float* base = g_ctx + (long)(b * H_ + h) * u * DH_ + e;
    for (int j = 0; j < u; j++) s += base[(long)j * DH_];
    g_mn[(b * H_ + h) * DH_ + e] = s / (float)u;
}

// ---------------- assemble Y rows: row 0 = mean, rows 1..u = ctx ----------------
__global__ void yrows_kernel(int u)
{
    int r = blockIdx.x;      // 0..u
    int b = blockIdx.y;
    int tid = threadIdx.x;   // 256 -> 4 d each
    float* out = g_Y + ((long)b * (u + 1) + r) * D_;
    #pragma unroll
    for (int q = 0; q < 4; q++) {
        int d = tid * 4 + q;
        int h = d >> 6, e = d & 63;
        float v = (r == 0) ? g_mn[(b * H_ + h) * DH_ + e]
                           : g_ctx[((long)(b * H_ + h) * u + (r - 1)) * DH_ + e];
        out[d] = v;
    }
}

// ---------------- broadcast base row to all T, then scatter idx rows ----------------
__global__ void bcast_kernel(float4* __restrict__ out, const float* __restrict__ O, int u)
{
    long i = (long)blockIdx.x * blockDim.x + threadIdx.x;
    long total = (long)B_ * T_ * (D_ / 4);
    if (i >= total) return;
    int d4 = (int)(i & 255);           // D/4 = 256
    long bt = i >> 8;
    int b = (int)(bt >> 12);           // T = 4096
    out[i] = reinterpret_cast<const float4*>(O + (long)b * (u + 1) * D_)[d4];
}

__global__ void scatter_kernel(float* __restrict__ out, const int* __restrict__ idx, int u)
{
    int j = blockIdx.x, b = blockIdx.y;
    int t = idx[j];
    const float4* src = reinterpret_cast<const float4*>(g_O + ((long)b * (u + 1) + 1 + j) * D_);
    float4* dst = reinterpret_cast<float4*>(out + ((long)b * T_ + t) * D_);
    dst[threadIdx.x] = src[threadIdx.x];   // 256 threads
}

// ---------------- host launch ----------------
static float* symaddr(const void* sym)
{
    void* p = nullptr;
    cudaGetSymbolAddress(&p, sym);
    return (float*)p;
}

extern "C" void kernel_launch(void* const* d_in, const int* in_sizes, int n_in,
                              void* d_out, int out_size)
{
    const float* x  = (const float*)d_in[0];
    const float* Wq = (const float*)d_in[1];
    const float* Wk = (const float*)d_in[2];
    const float* Wv = (const float*)d_in[3];
    const float* Wo = (const float*)d_in[4];
    const float* bo = (const float*)d_in[5];
    const int*  idx = (const int*)d_in[6];
    const int u = in_sizes[6];            // 41

    float* Xs = symaddr(g_Xs);
    float* Qs = symaddr(g_Qs);
    float* Qt = symaddr(g_Qt);
    float* S  = symaddr(g_S);
    float* AX = symaddr(g_AX);
    float* Y  = symaddr(g_Y);
    float* O  = symaddr(g_O);

    const int MQ = H_ * u;                // 656

    // 1) gather query rows
    gather_kernel<<<dim3(u, B_), 256>>>(x, idx, u);

    // 2) Qs = Xs @ Wq^T   (M=B*u, N=D, K=D)
    sgemm<true><<<dim3(D_ / 128, (B_ * u + 127) / 128, 1), 256>>>(
        Xs, Wq, Qs, B_ * u, D_, D_, 0, 0, 0, nullptr);

    // 3) Qt = scale * Qs_h @ Wk_h
    qt_kernel<<<dim3(u, H_, B_), 256>>>(Wk, u);

    // 4) S[b] = Qt[b] @ x[b]^T   (batched NT: M=MQ, N=T, K=D)
    sgemm<true><<<dim3(T_ / 128, (MQ + 127) / 128, B_), 256>>>(
        Qt, x, S, MQ, T_, D_, (long)MQ * D_, (long)T_ * D_, (long)MQ * T_, nullptr);

    // 5) softmax rows
    softmax_kernel<<<B_ * MQ, 256>>>();

    // 6) AX[b] = attn[b] @ x[b]   (batched NN: M=MQ, N=D, K=T)
    sgemm<false><<<dim3(D_ / 128, (MQ + 127) / 128, B_), 256>>>(
        S, x, AX, MQ, D_, T_, (long)MQ * T_, (long)T_ * D_, (long)MQ * D_, nullptr);

    // 7) ctx = AX @ Wv_h^T, 8) mean, 9) assemble rows
    ctx_kernel<<<dim3(u, H_, B_), 64>>>(Wv, u);
    mean_kernel<<<dim3(H_, B_), 64>>>(u);
    yrows_kernel<<<dim3(u + 1, B_), 256>>>(u);

    // 10) O = Y @ Wo^T + bo   (M=B*(u+1), N=D, K=D)
    sgemm<true><<<dim3(D_ / 128, (B_ * (u + 1) + 127) / 128, 1), 256>>>(
        Y, Wo, O, B_ * (u + 1), D_, D_, 0, 0, 0, bo);

    // 11) broadcast base rows, 12) overwrite idx rows
    long total4 = (long)B_ * T_ * (D_ / 4);
    bcast_kernel<<<(unsigned)((total4 + 255) / 256), 256>>>((float4*)d_out, O, u);
    scatter_kernel<<<dim3(u, B_), 256>>>((float*)d_out, idx, u);
}

// round 6
// speedup vs baseline: 1.2956x; 1.2956x over previous
#include <cuda_runtime.h>
#include <cuda_fp16.h>
#include <cstdint>

// Problem constants
#define B_  8
#define T_  4096
#define D_  1024
#define H_  16
#define DH_ 64
#define UMAX 44
#define MP_ 768     // padded M rows per batch (>= H*u = 656), multiple of 128

// ---------------- scratch (device globals; zero-initialized, no runtime alloc) ----
__device__ float  g_Xs [B_*UMAX*D_];
__device__ float  g_Qs [B_*UMAX*D_];
__device__ __half g_Qthi[(long)B_*MP_*D_];     // padded rows stay zero
__device__ __half g_Qtlo[(long)B_*MP_*D_];
__device__ __half g_Xhi [(long)B_*T_*D_];
__device__ __half g_Xlo [(long)B_*T_*D_];
__device__ __half g_XThi[(long)B_*D_*T_];      // x transposed [b][d][t]
__device__ __half g_XTlo[(long)B_*D_*T_];
__device__ float  g_S   [(long)B_*MP_*T_];     // scores (fp32)
__device__ __half g_Phi [(long)B_*MP_*T_];     // attn probs split
__device__ __half g_Plo [(long)B_*MP_*T_];
__device__ float  g_AX  [(long)B_*MP_*D_];
__device__ float  g_ctx [B_*H_*UMAX*DH_];
__device__ float  g_mn  [B_*H_*DH_];
__device__ float  g_Y   [B_*(UMAX+1)*D_];
__device__ float  g_O   [B_*(UMAX+1)*D_];

// ================= helpers =================
__device__ __forceinline__ uint32_t smem_u32(const void* p) {
    uint32_t a;
    asm("{ .reg .u64 t; cvta.to.shared.u64 t, %1; cvt.u32.u64 %0, t; }" : "=r"(a) : "l"(p));
    return a;
}
__device__ __forceinline__ void ldsm4(uint32_t& r0, uint32_t& r1, uint32_t& r2, uint32_t& r3,
                                      uint32_t a) {
    asm volatile("ldmatrix.sync.aligned.m8n8.x4.shared.b16 {%0,%1,%2,%3}, [%4];"
                 : "=r"(r0), "=r"(r1), "=r"(r2), "=r"(r3) : "r"(a));
}
__device__ __forceinline__ void mma16816(float* d, const uint32_t* a, const uint32_t* b) {
    asm volatile("mma.sync.aligned.m16n8k16.row.col.f32.f16.f16.f32 "
                 "{%0,%1,%2,%3}, {%4,%5,%6,%7}, {%8,%9}, {%0,%1,%2,%3};"
                 : "+f"(d[0]), "+f"(d[1]), "+f"(d[2]), "+f"(d[3])
                 : "r"(a[0]), "r"(a[1]), "r"(a[2]), "r"(a[3]), "r"(b[0]), "r"(b[1]));
}
__device__ __forceinline__ void hsplit(float v, __half& h, __half& l) {
    h = __float2half_rn(v);
    l = __float2half_rn(v - __half2float(h));
}

// ================= split-fp16 NT tensor-core GEMM (mma.sync) =================
// C[b][m,n] = sum_k (Ahi+Alo)[m,k]*(Bhi+Blo)[n,k], lo*lo dropped.
// M,N multiples of 128, K multiple of 16. Both operands row-major, K contiguous (NT).
#define HK   16
#define HPAD 24
#define HMAT (128 * HPAD)   // halfs per matrix tile buffer

__global__ void __launch_bounds__(256)
hmma_gemm(const __half* __restrict__ Ahi, const __half* __restrict__ Alo,
          const __half* __restrict__ Bhi, const __half* __restrict__ Blo,
          float* __restrict__ C, int K, int N, long sA, long sB, long sC)
{
    __shared__ __half sm[2 * 4 * HMAT];   // 49152 bytes
    const int tid = threadIdx.x, lane = tid & 31, wid = tid >> 5;
    const int b = blockIdx.z;
    const int m0 = blockIdx.y * 128, n0 = blockIdx.x * 128;
    const int wm = (wid & 3) * 32, wn = (wid >> 2) * 64;

    const __half* srcs[4] = {
        Ahi + (long)b * sA + (long)m0 * K,
        Alo + (long)b * sA + (long)m0 * K,
        Bhi + (long)b * sB + (long)n0 * K,
        Blo + (long)b * sB + (long)n0 * K };
    float* Cb = C + (long)b * sC;

    const int lrow = tid >> 1;            // 0..127
    const int lcol = (tid & 1) * 8;       // 0 or 8
    const uint32_t sbase = smem_u32(sm);
    const uint32_t fr = lane & 15, fc = (lane >> 4) * 8;   // ldmatrix lane mapping

    float acc[2][8][4];
    #pragma unroll
    for (int i = 0; i < 2; i++)
        #pragma unroll
        for (int j = 0; j < 8; j++)
            #pragma unroll
            for (int q = 0; q < 4; q++) acc[i][j][q] = 0.f;

    const int NCH = K / HK;
    uint4 ld[4];

    auto LDG = [&](int c) {
        #pragma unroll
        for (int t = 0; t < 4; t++)
            ld[t] = *reinterpret_cast<const uint4*>(srcs[t] + (long)lrow * K + c * HK + lcol);
    };
    auto STS = [&](int buf) {
        #pragma unroll
        for (int t = 0; t < 4; t++)
            *reinterpret_cast<uint4*>(&sm[(buf * 4 + t) * HMAT + lrow * HPAD + lcol]) = ld[t];
    };
    auto COMPUTE = [&](int buf) {
        uint32_t ah[2][4], al[2][4], bh[8][2], bl[8][2];
        #pragma unroll
        for (int mt = 0; mt < 2; mt++) {
            uint32_t a0 = sbase + ((buf * 4 + 0) * HMAT + (wm + mt * 16 + fr) * HPAD + fc) * 2;
            ldsm4(ah[mt][0], ah[mt][1], ah[mt][2], ah[mt][3], a0);
            ldsm4(al[mt][0], al[mt][1], al[mt][2], al[mt][3], a0 + HMAT * 2);
        }
        #pragma unroll
        for (int p = 0; p < 4; p++) {
            uint32_t b0 = sbase + ((buf * 4 + 2) * HMAT + (wn + p * 16 + fr) * HPAD + fc) * 2;
            uint32_t r0, r1, r2, r3;
            ldsm4(r0, r1, r2, r3, b0);
            bh[2*p][0] = r0; bh[2*p+1][0] = r1; bh[2*p][1] = r2; bh[2*p+1][1] = r3;
            ldsm4(r0, r1, r2, r3, b0 + HMAT * 2);
            bl[2*p][0] = r0; bl[2*p+1][0] = r1; bl[2*p][1] = r2; bl[2*p+1][1] = r3;
        }
        #pragma unroll
        for (int mt = 0; mt < 2; mt++)
            #pragma unroll
            for (int nt = 0; nt < 8; nt++) {
                mma16816(acc[mt][nt], ah[mt], bh[nt]);
                mma16816(acc[mt][nt], ah[mt], bl[nt]);
                mma16816(acc[mt][nt], al[mt], bh[nt]);
            }
    };

    LDG(0); STS(0); __syncthreads();
    for (int c = 1; c < NCH; c++) {
        LDG(c);
        COMPUTE((c - 1) & 1);
        STS(c & 1);
        __syncthreads();
    }
    COMPUTE((NCH - 1) & 1);

    // epilogue: direct float2 stores from accumulators
    const int qr = lane >> 2, qc = (lane & 3) * 2;
    #pragma unroll
    for (int mt = 0; mt < 2; mt++)
        #pragma unroll
        for (int nt = 0; nt < 8; nt++) {
            long r = m0 + wm + mt * 16 + qr;
            int cc = n0 + wn + nt * 8 + qc;
            *reinterpret_cast<float2*>(&Cb[r * N + cc]) =
                make_float2(acc[mt][nt][0], acc[mt][nt][1]);
            *reinterpret_cast<float2*>(&Cb[(r + 8) * N + cc]) =
                make_float2(acc[mt][nt][2], acc[mt][nt][3]);
        }
}

// ---------------- SIMT SGEMM (tiny projections, fp32) ----------------
template<bool NT>
__global__ void __launch_bounds__(256, 2)
sgemm(const float* __restrict__ Ag, const float* __restrict__ Bg,
      float* __restrict__ Cg, int M, int N, int K,
      long sA, long sB, long sC, const float* __restrict__ bias)
{
    const int bb = blockIdx.z;
    const float* A  = Ag + (long)bb * sA;
    const float* Bp = Bg + (long)bb * sB;
    float*       C  = Cg + (long)bb * sC;

    __shared__ float As[8][128];
    __shared__ float Bs[8][128];

    const int m0 = blockIdx.y * 128;
    const int n0 = blockIdx.x * 128;
    const int tid = threadIdx.x;
    const int arow = tid >> 1;
    const int ak4  = (tid & 1) * 4;
    const int bk   = tid >> 5;
    const int bn4  = (tid & 31) * 4;

    float acc[8][8];
    #pragma unroll
    for (int i = 0; i < 8; i++)
        #pragma unroll
        for (int j = 0; j < 8; j++) acc[i][j] = 0.f;

    const int tm = (tid >> 4) * 8;
    const int tn = (tid & 15) * 8;

    for (int k0 = 0; k0 < K; k0 += 8) {
        {
            int gm = m0 + arow;
            float4 v = make_float4(0.f, 0.f, 0.f, 0.f);
            if (gm < M) v = *reinterpret_cast<const float4*>(A + (long)gm * K + k0 + ak4);
            As[ak4 + 0][arow] = v.x; As[ak4 + 1][arow] = v.y;
            As[ak4 + 2][arow] = v.z; As[ak4 + 3][arow] = v.w;
        }
        if (NT) {
            int gn = n0 + arow;
            float4 v = make_float4(0.f, 0.f, 0.f, 0.f);
            if (gn < N) v = *reinterpret_cast<const float4*>(Bp + (long)gn * K + k0 + ak4);
            Bs[ak4 + 0][arow] = v.x; Bs[ak4 + 1][arow] = v.y;
            Bs[ak4 + 2][arow] = v.z; Bs[ak4 + 3][arow] = v.w;
        } else {
            float4 v = *reinterpret_cast<const float4*>(Bp + (long)(k0 + bk) * N + n0 + bn4);
            *reinterpret_cast<float4*>(&Bs[bk][bn4]) = v;
        }
        __syncthreads();

        #pragma unroll
        for (int kk = 0; kk < 8; kk++) {
            float ar[8], br[8];
            *reinterpret_cast<float4*>(&ar[0]) = *reinterpret_cast<const float4*>(&As[kk][tm]);
            *reinterpret_cast<float4*>(&ar[4]) = *reinterpret_cast<const float4*>(&As[kk][tm + 4]);
            *reinterpret_cast<float4*>(&br[0]) = *reinterpret_cast<const float4*>(&Bs[kk][tn]);
            *reinterpret_cast<float4*>(&br[4]) = *reinterpret_cast<const float4*>(&Bs[kk][tn + 4]);
            #pragma unroll
            for (int i = 0; i < 8; i++)
                #pragma unroll
                for (int j = 0; j < 8; j++) acc[i][j] += ar[i] * br[j];
        }
        __syncthreads();
    }

    #pragma unroll
    for (int i = 0; i < 8; i++) {
        int gm = m0 + tm + i;
        if (gm >= M) break;
        #pragma unroll
        for (int j = 0; j < 8; j++) {
            int gn = n0 + tn + j;
            float v = acc[i][j];
            if (bias) v += bias[gn];
            C[(long)gm * N + gn] = v;
        }
    }
}

// ---------------- small kernels ----------------
// x -> fp16 hi/lo (natural [T,D] layout)
__global__ void split_x_kernel(const float* __restrict__ x)
{
    long i = ((long)blockIdx.x * blockDim.x + threadIdx.x);
    long n4 = (long)B_ * T_ * D_ / 4;
    if (i >= n4) return;
    float4 v = reinterpret_cast<const float4*>(x)[i];
    __half h[4], l[4];
    hsplit(v.x, h[0], l[0]); hsplit(v.y, h[1], l[1]);
    hsplit(v.z, h[2], l[2]); hsplit(v.w, h[3], l[3]);
    *reinterpret_cast<uint2*>(&g_Xhi[i * 4]) = *reinterpret_cast<uint2*>(h);
    *reinterpret_cast<uint2*>(&g_Xlo[i * 4]) = *reinterpret_cast<uint2*>(l);
}

// x -> transposed fp16 hi/lo: xT[b][d][t]
__global__ void xT_split_kernel(const float* __restrict__ x)
{
    __shared__ float tile[32][33];
    int b = blockIdx.z;
    int t0 = blockIdx.x * 32, d0 = blockIdx.y * 32;
    int tx = threadIdx.x, ty0 = threadIdx.y;   // 32 x 8
    #pragma unroll
    for (int j = 0; j < 4; j++) {
        int ty = ty0 + j * 8;
        tile[ty][tx] = x[((long)b * T_ + t0 + ty) * D_ + d0 + tx];
    }
    __syncthreads();
    #pragma unroll
    for (int j = 0; j < 4; j++) {
        int ty = ty0 + j * 8;
        float v = tile[tx][ty];   // = x[t0+tx][d0+ty]
        __half h, l; hsplit(v, h, l);
        long o = ((long)b * D_ + d0 + ty) * T_ + t0 + tx;
        g_XThi[o] = h; g_XTlo[o] = l;
    }
}

__global__ void gather_kernel(const float* __restrict__ x, const int* __restrict__ idx, int u)
{
    int j = blockIdx.x, b = blockIdx.y;
    int t = idx[j];
    const float4* src = reinterpret_cast<const float4*>(x + ((long)b * T_ + t) * D_);
    float4* dst = reinterpret_cast<float4*>(g_Xs + ((long)b * u + j) * D_);
    dst[threadIdx.x] = src[threadIdx.x];
}

// Qt row (h*u+j) of padded [MP_,D] = scale * Qs_h @ Wk_h, written as fp16 hi/lo
__global__ void qt_kernel(const float* __restrict__ Wk, int u)
{
    int j = blockIdx.x, h = blockIdx.y, b = blockIdx.z;
    __shared__ float q[DH_];
    int tid = threadIdx.x;   // 256
    if (tid < DH_) q[tid] = g_Qs[((long)b * u + j) * D_ + h * DH_ + tid];
    __syncthreads();

    const float* W = Wk + (long)h * DH_ * D_;
    float acc[4] = {0.f, 0.f, 0.f, 0.f};
    for (int c = 0; c < DH_; c++) {
        float qv = q[c];
        const float* wr = W + (long)c * D_;
        #pragma unroll
        for (int r = 0; r < 4; r++) acc[r] += qv * wr[tid + r * 256];
    }
    long base = ((long)b * MP_ + h * u + j) * D_;
    const float scale = 0.125f;
    #pragma unroll
    for (int r = 0; r < 4; r++) {
        __half hh, ll; hsplit(acc[r] * scale, hh, ll);
        g_Qthi[base + tid + r * 256] = hh;
        g_Qtlo[base + tid + r * 256] = ll;
    }
}

// softmax over T on real rows of g_S; write P as fp16 hi/lo
__global__ void softmax_kernel(int u)
{
    int MQ = H_ * u;
    int r = blockIdx.x % MQ, b = blockIdx.x / MQ;
    long row = (long)b * MP_ + r;
    const float* s = g_S + row * T_;
    __half* ph = g_Phi + row * T_;
    __half* pl = g_Plo + row * T_;
    int tid = threadIdx.x;   // 256
    __shared__ float red[256];

    float mx = -1e30f;
    for (int t = tid; t < T_; t += 256) mx = fmaxf(mx, s[t]);
    red[tid] = mx; __syncthreads();
    for (int o = 128; o > 0; o >>= 1) { if (tid < o) red[tid] = fmaxf(red[tid], red[tid + o]); __syncthreads(); }
    mx = red[0]; __syncthreads();

    float sum = 0.f;
    for (int t = tid; t < T_; t += 256) sum += __expf(s[t] - mx);
    red[tid] = sum; __syncthreads();
    for (int o = 128; o > 0; o >>= 1) { if (tid < o) red[tid] += red[tid + o]; __syncthreads(); }
    float inv = 1.f / red[0];
    for (int t = tid; t < T_; t += 256) {
        float p = __expf(s[t] - mx) * inv;
        __half hh, ll; hsplit(p, hh, ll);
        ph[t] = hh; pl[t] = ll;
    }
}

// ctx[b,h,j,:] = AX[row] @ Wv_h^T
__global__ void ctx_kernel(const float* __restrict__ Wv, int u)
{
    int j = blockIdx.x, h = blockIdx.y, b = blockIdx.z;
    __shared__ float ax[D_];
    int tid = threadIdx.x;   // 64
    const float* AXrow = g_AX + ((long)b * MP_ + h * u + j) * D_;
    for (int i = tid; i < D_ / 4; i += 64)
        reinterpret_cast<float4*>(ax)[i] = reinterpret_cast<const float4*>(AXrow)[i];
    __syncthreads();

    const float* wr = Wv + (long)(h * DH_ + tid) * D_;
    float acc = 0.f;
    #pragma unroll 4
    for (int d4 = 0; d4 < D_ / 4; d4++) {
        float4 w = reinterpret_cast<const float4*>(wr)[d4];
        float4 a = reinterpret_cast<const float4*>(ax)[d4];
        acc += a.x * w.x + a.y * w.y + a.z * w.z + a.w * w.w;
    }
    g_ctx[((long)(b * H_ + h) * u + j) * DH_ + tid] = acc;
}

__global__ void mean_kernel(int u)
{
    int h = blockIdx.x, b = blockIdx.y;
    int e = threadIdx.x;   // 64
    float s = 0.f;
    const float* base = g_ctx + (long)(b * H_ + h) * u * DH_ + e;
    for (int j = 0; j < u; j++) s += base[(long)j * DH_];
    g_mn[(b * H_ + h) * DH_ + e] = s / (float)u;
}

__global__ void yrows_kernel(int u)
{
    int r = blockIdx.x, b = blockIdx.y;
    int tid = threadIdx.x;   // 256
    float* out = g_Y + ((long)b * (u + 1) + r) * D_;
    #pragma unroll
    for (int q = 0; q < 4; q++) {
        int d = tid * 4 + q;
        int h = d >> 6, e = d & 63;
        float v = (r == 0) ? g_mn[(b * H_ + h) * DH_ + e]
                           : g_ctx[((long)(b * H_ + h) * u + (r - 1)) * DH_ + e];
        out[d] = v;
    }
}

__global__ void bcast_kernel(float4* __restrict__ out, const float* __restrict__ O, int u)
{
    long i = (long)blockIdx.x * blockDim.x + threadIdx.x;
    long total = (long)B_ * T_ * (D_ / 4);
    if (i >= total) return;
    int d4 = (int)(i & 255);
    long bt = i >> 8;
    int b = (int)(bt >> 12);
    out[i] = reinterpret_cast<const float4*>(O + (long)b * (u + 1) * D_)[d4];
}

__global__ void scatter_kernel(float* __restrict__ out, const int* __restrict__ idx, int u)
{
    int j = blockIdx.x, b = blockIdx.y;
    int t = idx[j];
    const float4* src = reinterpret_cast<const float4*>(g_O + ((long)b * (u + 1) + 1 + j) * D_);
    float4* dst = reinterpret_cast<float4*>(out + ((long)b * T_ + t) * D_);
    dst[threadIdx.x] = src[threadIdx.x];
}

// ---------------- host launch ----------------
template<typename Tp>
static Tp* symaddr_t(const void* sym)
{
    void* p = nullptr;
    cudaGetSymbolAddress(&p, sym);
    return (Tp*)p;
}

extern "C" void kernel_launch(void* const* d_in, const int* in_sizes, int n_in,
                              void* d_out, int out_size)
{
    const float* x  = (const float*)d_in[0];
    const float* Wq = (const float*)d_in[1];
    const float* Wk = (const float*)d_in[2];
    const float* Wv = (const float*)d_in[3];
    const float* Wo = (const float*)d_in[4];
    const float* bo = (const float*)d_in[5];
    const int*  idx = (const int*)d_in[6];
    const int u = in_sizes[6];            // 41

    float* Xs = symaddr_t<float>(g_Xs);
    float* Qs = symaddr_t<float>(g_Qs);
    float* S  = symaddr_t<float>(g_S);
    float* AX = symaddr_t<float>(g_AX);
    float* Y  = symaddr_t<float>(g_Y);
    float* O  = symaddr_t<float>(g_O);
    __half* Qthi = symaddr_t<__half>(g_Qthi);
    __half* Qtlo = symaddr_t<__half>(g_Qtlo);
    __half* Xhi  = symaddr_t<__half>(g_Xhi);
    __half* Xlo  = symaddr_t<__half>(g_Xlo);
    __half* XThi = symaddr_t<__half>(g_XThi);
    __half* XTlo = symaddr_t<__half>(g_XTlo);
    __half* Phi  = symaddr_t<__half>(g_Phi);
    __half* Plo  = symaddr_t<__half>(g_Plo);

    const int MQ = H_ * u;                // 656

    // 1) gather query rows; fp16 split conversions of x
    gather_kernel<<<dim3(u, B_), 256>>>(x, idx, u);
    {
        long n4 = (long)B_ * T_ * D_ / 4;
        split_x_kernel<<<(unsigned)((n4 + 255) / 256), 256>>>(x);
    }
    xT_split_kernel<<<dim3(T_ / 32, D_ / 32, B_), dim3(32, 8)>>>(x);

    // 2) Qs = Xs @ Wq^T  (SIMT fp32, tiny)
    sgemm<true><<<dim3(D_ / 128, (B_ * u + 127) / 128, 1), 256>>>(
        Xs, Wq, Qs, B_ * u, D_, D_, 0, 0, 0, nullptr);

    // 3) Qt = scale * Qs_h @ Wk_h  -> fp16 hi/lo (padded rows stay zero)
    qt_kernel<<<dim3(u, H_, B_), 256>>>(Wk, u);

    // 4) S[b] = Qt[b] @ x[b]^T   (split-fp16 mma.sync: M=768, N=4096, K=1024)
    hmma_gemm<<<dim3(T_ / 128, MP_ / 128, B_), 256>>>(
        Qthi, Qtlo, Xhi, Xlo, S, D_, T_,
        (long)MP_ * D_, (long)T_ * D_, (long)MP_ * T_);

    // 5) softmax -> P fp16 hi/lo
    softmax_kernel<<<B_ * MQ, 256>>>(u);

    // 6) AX[b] = P[b] @ x[b]  via NT with xT  (M=768, N=1024, K=4096)
    hmma_gemm<<<dim3(D_ / 128, MP_ / 128, B_), 256>>>(
        Phi, Plo, XThi, XTlo, AX, T_, D_,
        (long)MP_ * T_, (long)D_ * T_, (long)MP_ * D_);

    // 7-9) ctx, mean, assemble rows
    ctx_kernel<<<dim3(u, H_, B_), 64>>>(Wv, u);
    mean_kernel<<<dim3(H_, B_), 64>>>(u);
    yrows_kernel<<<dim3(u + 1, B_), 256>>>(u);

    // 10) O = Y @ Wo^T + bo  (SIMT fp32, tiny)
    sgemm<true><<<dim3(D_ / 128, (B_ * (u + 1) + 127) / 128, 1), 256>>>(
        Y, Wo, O, B_ * (u + 1), D_, D_, 0, 0, 0, bo);

    // 11-12) broadcast + scatter
    long total4 = (long)B_ * T_ * (D_ / 4);
    bcast_kernel<<<(unsigned)((total4 + 255) / 256), 256>>>((float4*)d_out, O, u);
    scatter_kernel<<<dim3(u, B_), 256>>>((float*)d_out, idx, u);
}

// round 7
// speedup vs baseline: 2.9218x; 2.2552x over previous
#include <cuda_runtime.h>
#include <cuda_fp16.h>
#include <cstdint>

// Problem constants
#define B_  8
#define T_  4096
#define D_  1024
#define H_  16
#define DH_ 64
#define UMAX 44
#define MP_ 768     // padded M rows per batch (>= H*u = 656), multiple of 128

// ---------------- scratch (device globals; zero-initialized) ----------------
__device__ float  g_Xs [B_*UMAX*D_];
__device__ float  g_Qs [B_*UMAX*D_];
__device__ __half g_Qthi[(long)B_*MP_*D_];     // padded rows stay zero
__device__ __half g_Xhi [(long)B_*T_*D_];
__device__ __half g_Xlo [(long)B_*T_*D_];
__device__ __half g_XThi[(long)B_*D_*T_];      // x transposed [b][d][t]
__device__ __half g_XTlo[(long)B_*D_*T_];
__device__ float  g_S   [(long)B_*MP_*T_];     // scores (fp32)
__device__ __half g_Phi [(long)B_*MP_*T_];     // attn probs fp16 (padded rows zero)
__device__ float  g_AX  [(long)B_*MP_*D_];
__device__ float  g_ctx [B_*H_*UMAX*DH_];
__device__ float  g_mn  [B_*H_*DH_];
__device__ float  g_Y   [B_*(UMAX+1)*D_];
__device__ float  g_O   [B_*(UMAX+1)*D_];

// ================= helpers =================
__device__ __forceinline__ uint32_t smem_u32(const void* p) {
    uint32_t a;
    asm("{ .reg .u64 t; cvta.to.shared.u64 t, %1; cvt.u32.u64 %0, t; }" : "=r"(a) : "l"(p));
    return a;
}
__device__ __forceinline__ void ldsm4(uint32_t& r0, uint32_t& r1, uint32_t& r2, uint32_t& r3,
                                      uint32_t a) {
    asm volatile("ldmatrix.sync.aligned.m8n8.x4.shared.b16 {%0,%1,%2,%3}, [%4];"
                 : "=r"(r0), "=r"(r1), "=r"(r2), "=r"(r3) : "r"(a));
}
__device__ __forceinline__ void mma16816(float* d, const uint32_t* a, const uint32_t* b) {
    asm volatile("mma.sync.aligned.m16n8k16.row.col.f32.f16.f16.f32 "
                 "{%0,%1,%2,%3}, {%4,%5,%6,%7}, {%8,%9}, {%0,%1,%2,%3};"
                 : "+f"(d[0]), "+f"(d[1]), "+f"(d[2]), "+f"(d[3])
                 : "r"(a[0]), "r"(a[1]), "r"(a[2]), "r"(a[3]), "r"(b[0]), "r"(b[1]));
}
__device__ __forceinline__ void hsplit(float v, __half& h, __half& l) {
    h = __float2half_rn(v);
    l = __float2half_rn(v - __half2float(h));
}

// ================= 2-term split-fp16 NT tensor-core GEMM =================
// C[b][m,n] = sum_k Ah[m,k]*(Bhi+Blo)[n,k]  (A plain fp16, B split)
// M,N multiples of 128, K multiple of 16. Row-major, K contiguous (NT).
#define HK   16
#define HPAD 24
#define HMAT (128 * HPAD)   // halfs per matrix tile buffer

__global__ void __launch_bounds__(256)
hmma_gemm(const __half* __restrict__ Ah, const __half* __restrict__ Bhi,
          const __half* __restrict__ Blo,
          float* __restrict__ C, int K, int N, long sA, long sB, long sC)
{
    __shared__ __half sm[2 * 3 * HMAT];   // 36864 bytes
    const int tid = threadIdx.x, lane = tid & 31, wid = tid >> 5;
    const int b = blockIdx.z;
    const int m0 = blockIdx.y * 128, n0 = blockIdx.x * 128;
    const int wm = (wid & 3) * 32, wn = (wid >> 2) * 64;

    const __half* srcs[3] = {
        Ah  + (long)b * sA + (long)m0 * K,
        Bhi + (long)b * sB + (long)n0 * K,
        Blo + (long)b * sB + (long)n0 * K };
    float* Cb = C + (long)b * sC;

    const int lrow = tid >> 1;            // 0..127
    const int lcol = (tid & 1) * 8;       // 0 or 8
    const uint32_t sbase = smem_u32(sm);
    const uint32_t fr = lane & 15, fc = (lane >> 4) * 8;

    float acc[2][8][4];
    #pragma unroll
    for (int i = 0; i < 2; i++)
        #pragma unroll
        for (int j = 0; j < 8; j++)
            #pragma unroll
            for (int q = 0; q < 4; q++) acc[i][j][q] = 0.f;

    const int NCH = K / HK;
    uint4 ld[3];

    auto LDG = [&](int c) {
        #pragma unroll
        for (int t = 0; t < 3; t++)
            ld[t] = *reinterpret_cast<const uint4*>(srcs[t] + (long)lrow * K + c * HK + lcol);
    };
    auto STS = [&](int buf) {
        #pragma unroll
        for (int t = 0; t < 3; t++)
            *reinterpret_cast<uint4*>(&sm[(buf * 3 + t) * HMAT + lrow * HPAD + lcol]) = ld[t];
    };
    auto COMPUTE = [&](int buf) {
        uint32_t a8[2][4], bh[8][2], bl[8][2];
        #pragma unroll
        for (int mt = 0; mt < 2; mt++) {
            uint32_t a0 = sbase + ((buf * 3 + 0) * HMAT + (wm + mt * 16 + fr) * HPAD + fc) * 2;
            ldsm4(a8[mt][0], a8[mt][1], a8[mt][2], a8[mt][3], a0);
        }
        #pragma unroll
        for (int p = 0; p < 4; p++) {
            uint32_t b0 = sbase + ((buf * 3 + 1) * HMAT + (wn + p * 16 + fr) * HPAD + fc) * 2;
            uint32_t r0, r1, r2, r3;
            ldsm4(r0, r1, r2, r3, b0);
            bh[2*p][0] = r0; bh[2*p+1][0] = r1; bh[2*p][1] = r2; bh[2*p+1][1] = r3;
            ldsm4(r0, r1, r2, r3, b0 + HMAT * 2);
            bl[2*p][0] = r0; bl[2*p+1][0] = r1; bl[2*p][1] = r2; bl[2*p+1][1] = r3;
        }
        #pragma unroll
        for (int mt = 0; mt < 2; mt++)
            #pragma unroll
            for (int nt = 0; nt < 8; nt++) {
                mma16816(acc[mt][nt], a8[mt], bh[nt]);
                mma16816(acc[mt][nt], a8[mt], bl[nt]);
            }
    };

    LDG(0); STS(0); __syncthreads();
    for (int c = 1; c < NCH; c++) {
        LDG(c);
        COMPUTE((c - 1) & 1);
        STS(c & 1);
        __syncthreads();
    }
    COMPUTE((NCH - 1) & 1);

    const int qr = lane >> 2, qc = (lane & 3) * 2;
    #pragma unroll
    for (int mt = 0; mt < 2; mt++)
        #pragma unroll
        for (int nt = 0; nt < 8; nt++) {
            long r = m0 + wm + mt * 16 + qr;
            int cc = n0 + wn + nt * 8 + qc;
            *reinterpret_cast<float2*>(&Cb[r * N + cc]) =
                make_float2(acc[mt][nt][0], acc[mt][nt][1]);
            *reinterpret_cast<float2*>(&Cb[(r + 8) * N + cc]) =
                make_float2(acc[mt][nt][2], acc[mt][nt][3]);
        }
}

// ================= batched 64x64-tile SIMT GEMM =================
// NT: C[m,n] = sum_k A[m,k]*B[n,k]; NN: C[m,n] = sum_k A[m,k]*B[k,n]
// Batch z decomposes as zb = z/ZH, zh = z%ZH with separate strides.
// N multiple of 64; M arbitrary (guarded); K multiple of 16.
template<bool NT, bool HALF_OUT>
__global__ void __launch_bounds__(256)
sgemm64(const float* __restrict__ A, const float* __restrict__ B, void* __restrict__ Cv,
        int M, int N, int K, int lda, int ldb, int ldc, int ZH,
        long sAb, long sAh, long sBb, long sBh, long sCb, long sCh,
        const float* __restrict__ bias, float alpha)
{
    const int zb = blockIdx.z / ZH, zh = blockIdx.z % ZH;
    A += (long)zb * sAb + (long)zh * sAh;
    B += (long)zb * sBb + (long)zh * sBh;
    const long coff = (long)zb * sCb + (long)zh * sCh;

    __shared__ float As[16][68];
    __shared__ float Bs[16][68];

    const int m0 = blockIdx.y * 64, n0 = blockIdx.x * 64;
    const int tid = threadIdx.x;
    const int lr = tid >> 2;             // 0..63
    const int lk = (tid & 3) * 4;        // 0,4,8,12
    const int bk = tid >> 4;             // 0..15  (NN)
    const int bn = (tid & 15) * 4;       // 0..60  (NN)
    const int tm = (tid >> 4) * 4, tn = (tid & 15) * 4;

    float acc[4][4];
    #pragma unroll
    for (int i = 0; i < 4; i++)
        #pragma unroll
        for (int j = 0; j < 4; j++) acc[i][j] = 0.f;

    for (int k0 = 0; k0 < K; k0 += 16) {
        {   // A tile -> As[k][m]
            float4 v = make_float4(0.f, 0.f, 0.f, 0.f);
            int gm = m0 + lr;
            if (gm < M) v = *reinterpret_cast<const float4*>(A + (long)gm * lda + k0 + lk);
            As[lk + 0][lr] = v.x; As[lk + 1][lr] = v.y;
            As[lk + 2][lr] = v.z; As[lk + 3][lr] = v.w;
        }
        if (NT) {
            float4 v = *reinterpret_cast<const float4*>(B + (long)(n0 + lr) * ldb + k0 + lk);
            Bs[lk + 0][lr] = v.x; Bs[lk + 1][lr] = v.y;
            Bs[lk + 2][lr] = v.z; Bs[lk + 3][lr] = v.w;
        } else {
            float4 v = *reinterpret_cast<const float4*>(B + (long)(k0 + bk) * ldb + n0 + bn);
            *reinterpret_cast<float4*>(&Bs[bk][bn]) = v;
        }
        __syncthreads();

        #pragma unroll
        for (int kk = 0; kk < 16; kk++) {
            float ar[4], br[4];
            *reinterpret_cast<float4*>(ar) = *reinterpret_cast<const float4*>(&As[kk][tm]);
            *reinterpret_cast<float4*>(br) = *reinterpret_cast<const float4*>(&Bs[kk][tn]);
            #pragma unroll
            for (int i = 0; i < 4; i++)
                #pragma unroll
                for (int j = 0; j < 4; j++) acc[i][j] += ar[i] * br[j];
        }
        __syncthreads();
    }

    #pragma unroll
    for (int i = 0; i < 4; i++) {
        int gm = m0 + tm + i;
        if (gm >= M) break;
        #pragma unroll
        for (int j = 0; j < 4; j++) {
            int gn = n0 + tn + j;
            float v = acc[i][j] * alpha;
            if (bias) v += bias[gn];
            if (HALF_OUT)
                ((__half*)Cv)[coff + (long)gm * ldc + gn] = __float2half_rn(v);
            else
                ((float*)Cv)[coff + (long)gm * ldc + gn] = v;
        }
    }
}

// ---------------- small kernels ----------------
__global__ void split_x_kernel(const float* __restrict__ x)
{
    long i = ((long)blockIdx.x * blockDim.x + threadIdx.x);
    long n4 = (long)B_ * T_ * D_ / 4;
    if (i >= n4) return;
    float4 v = reinterpret_cast<const float4*>(x)[i];
    __half h[4], l[4];
    hsplit(v.x, h[0], l[0]); hsplit(v.y, h[1], l[1]);
    hsplit(v.z, h[2], l[2]); hsplit(v.w, h[3], l[3]);
    *reinterpret_cast<uint2*>(&g_Xhi[i * 4]) = *reinterpret_cast<uint2*>(h);
    *reinterpret_cast<uint2*>(&g_Xlo[i * 4]) = *reinterpret_cast<uint2*>(l);
}

__global__ void xT_split_kernel(const float* __restrict__ x)
{
    __shared__ float tile[32][33];
    int b = blockIdx.z;
    int t0 = blockIdx.x * 32, d0 = blockIdx.y * 32;
    int tx = threadIdx.x, ty0 = threadIdx.y;   // 32 x 8
    #pragma unroll
    for (int j = 0; j < 4; j++) {
        int ty = ty0 + j * 8;
        tile[ty][tx] = x[((long)b * T_ + t0 + ty) * D_ + d0 + tx];
    }
    __syncthreads();
    #pragma unroll
    for (int j = 0; j < 4; j++) {
        int ty = ty0 + j * 8;
        float v = tile[tx][ty];   // = x[t0+tx][d0+ty]
        __half h, l; hsplit(v, h, l);
        long o = ((long)b * D_ + d0 + ty) * T_ + t0 + tx;
        g_XThi[o] = h; g_XTlo[o] = l;
    }
}

__global__ void gather_kernel(const float* __restrict__ x, const int* __restrict__ idx, int u)
{
    int j = blockIdx.x, b = blockIdx.y;
    int t = idx[j];
    const float4* src = reinterpret_cast<const float4*>(x + ((long)b * T_ + t) * D_);
    float4* dst = reinterpret_cast<float4*>(g_Xs + ((long)b * u + j) * D_);
    dst[threadIdx.x] = src[threadIdx.x];
}

// softmax over T on real rows of g_S; write P as fp16
__global__ void softmax_kernel(int u)
{
    int MQ = H_ * u;
    int r = blockIdx.x % MQ, b = blockIdx.x / MQ;
    long row = (long)b * MP_ + r;
    const float* s = g_S + row * T_;
    __half* ph = g_Phi + row * T_;
    int tid = threadIdx.x;   // 256
    __shared__ float red[256];

    float mx = -1e30f;
    for (int t = tid; t < T_; t += 256) mx = fmaxf(mx, s[t]);
    red[tid] = mx; __syncthreads();
    for (int o = 128; o > 0; o >>= 1) { if (tid < o) red[tid] = fmaxf(red[tid], red[tid + o]); __syncthreads(); }
    mx = red[0]; __syncthreads();

    float sum = 0.f;
    for (int t = tid; t < T_; t += 256) sum += __expf(s[t] - mx);
    red[tid] = sum; __syncthreads();
    for (int o = 128; o > 0; o >>= 1) { if (tid < o) red[tid] += red[tid + o]; __syncthreads(); }
    float inv = 1.f / red[0];
    for (int t = tid; t < T_; t += 256)
        ph[t] = __float2half_rn(__expf(s[t] - mx) * inv);
}

__global__ void mean_kernel(int u)
{
    int h = blockIdx.x, b = blockIdx.y;
    int e = threadIdx.x;   // 64
    float s = 0.f;
    const float* base = g_ctx + (long)(b * H_ + h) * u * DH_ + e;
    for (int j = 0; j < u; j++) s += base[(long)j * DH_];
    g_mn[(b * H_ + h) * DH_ + e] = s / (float)u;
}

__global__ void yrows_kernel(int u)
{
    int r = blockIdx.x, b = blockIdx.y;
    int tid = threadIdx.x;   // 256
    float* out = g_Y + ((long)b * (u + 1) + r) * D_;
    #pragma unroll
    for (int q = 0; q < 4; q++) {
        int d = tid * 4 + q;
        int h = d >> 6, e = d & 63;
        float v = (r == 0) ? g_mn[(b * H_ + h) * DH_ + e]
                           : g_ctx[((long)(b * H_ + h) * u + (r - 1)) * DH_ + e];
        out[d] = v;
    }
}

__global__ void bcast_kernel(float4* __restrict__ out, const float* __restrict__ O, int u)
{
    long i = (long)blockIdx.x * blockDim.x + threadIdx.x;
    long total = (long)B_ * T_ * (D_ / 4);
    if (i >= total) return;
    int d4 = (int)(i & 255);
    long bt = i >> 8;
    int b = (int)(bt >> 12);
    out[i] = reinterpret_cast<const float4*>(O + (long)b * (u + 1) * D_)[d4];
}

__global__ void scatter_kernel(float* __restrict__ out, const int* __restrict__ idx, int u)
{
    int j = blockIdx.x, b = blockIdx.y;
    int t = idx[j];
    const float4* src = reinterpret_cast<const float4*>(g_O + ((long)b * (u + 1) + 1 + j) * D_);
    float4* dst = reinterpret_cast<float4*>(out + ((long)b * T_ + t) * D_);
    dst[threadIdx.x] = src[threadIdx.x];
}

// ---------------- host launch ----------------
template<typename Tp>
static Tp* symaddr_t(const void* sym)
{
    void* p = nullptr;
    cudaGetSymbolAddress(&p, sym);
    return (Tp*)p;
}

extern "C" void kernel_launch(void* const* d_in, const int* in_sizes, int n_in,
                              void* d_out, int out_size)
{
    const float* x  = (const float*)d_in[0];
    const float* Wq = (const float*)d_in[1];
    const float* Wk = (const float*)d_in[2];
    const float* Wv = (const float*)d_in[3];
    const float* Wo = (const float*)d_in[4];
    const float* bo = (const float*)d_in[5];
    const int*  idx = (const int*)d_in[6];
    const int u = in_sizes[6];            // 41

    float* Xs = symaddr_t<float>(g_Xs);
    float* Qs = symaddr_t<float>(g_Qs);
    float* S  = symaddr_t<float>(g_S);
    float* AX = symaddr_t<float>(g_AX);
    float* Y  = symaddr_t<float>(g_Y);
    float* O  = symaddr_t<float>(g_O);
    float* CT = symaddr_t<float>(g_ctx);
    __half* Qthi = symaddr_t<__half>(g_Qthi);
    __half* Xhi  = symaddr_t<__half>(g_Xhi);
    __half* Xlo  = symaddr_t<__half>(g_Xlo);
    __half* XThi = symaddr_t<__half>(g_XThi);
    __half* XTlo = symaddr_t<__half>(g_XTlo);
    __half* Phi  = symaddr_t<__half>(g_Phi);

    const int MQ = H_ * u;                // 656

    // 1) gather query rows; fp16 split conversions of x
    gather_kernel<<<dim3(u, B_), 256>>>(x, idx, u);
    {
        long n4 = (long)B_ * T_ * D_ / 4;
        split_x_kernel<<<(unsigned)((n4 + 255) / 256), 256>>>(x);
    }
    xT_split_kernel<<<dim3(T_ / 32, D_ / 32, B_), dim3(32, 8)>>>(x);

    // 2) Qs = Xs @ Wq^T  (M=B*u, N=D, K=D)
    sgemm64<true, false><<<dim3(D_ / 64, (B_ * u + 63) / 64, 1), 256>>>(
        Xs, Wq, Qs, B_ * u, D_, D_, D_, D_, D_, 1,
        0, 0, 0, 0, 0, 0, nullptr, 1.f);

    // 3) Qt_h = scale * Qs_h @ Wk_h  (batched over (b,h): M=u, N=D, K=DH) -> fp16
    sgemm64<false, true><<<dim3(D_ / 64, 1, B_ * H_), 256>>>(
        Qs, Wk, Qthi, u, D_, DH_, D_, D_, D_, H_,
        (long)u * D_, DH_, 0, (long)DH_ * D_, (long)MP_ * D_, (long)u * D_,
        nullptr, 0.125f);

    // 4) S[b] = Qt[b] @ x[b]^T  (2-term split-fp16 mma: M=768, N=4096, K=1024)
    hmma_gemm<<<dim3(T_ / 128, MP_ / 128, B_), 256>>>(
        Qthi, Xhi, Xlo, S, D_, T_,
        (long)MP_ * D_, (long)T_ * D_, (long)MP_ * T_);

    // 5) softmax -> P fp16
    softmax_kernel<<<B_ * MQ, 256>>>(u);

    // 6) AX[b] = P[b] @ x[b] via NT with xT  (M=768, N=1024, K=4096)
    hmma_gemm<<<dim3(D_ / 128, MP_ / 128, B_), 256>>>(
        Phi, XThi, XTlo, AX, T_, D_,
        (long)MP_ * T_, (long)D_ * T_, (long)MP_ * D_);

    // 7) ctx_h = AX_h @ Wv_h^T  (batched over (b,h): M=u, N=DH, K=D)
    sgemm64<true, false><<<dim3(1, 1, B_ * H_), 256>>>(
        AX, Wv, CT, u, DH_, D_, D_, D_, DH_, H_,
        (long)MP_ * D_, (long)u * D_, 0, (long)DH_ * D_,
        (long)H_ * u * DH_, (long)u * DH_, nullptr, 1.f);

    // 8-9) mean, assemble rows
    mean_kernel<<<dim3(H_, B_), 64>>>(u);
    yrows_kernel<<<dim3(u + 1, B_), 256>>>(u);

    // 10) O = Y @ Wo^T + bo  (M=B*(u+1), N=D, K=D)
    sgemm64<true, false><<<dim3(D_ / 64, (B_ * (u + 1) + 63) / 64, 1), 256>>>(
        Y, Wo, O, B_ * (u + 1), D_, D_, D_, D_, D_, 1,
        0, 0, 0, 0, 0, 0, bo, 1.f);

    // 11-12) broadcast + scatter
    long total4 = (long)B_ * T_ * (D_ / 4);
    bcast_kernel<<<(unsigned)((total4 + 255) / 256), 256>>>((float4*)d_out, O, u);
    scatter_kernel<<<dim3(u, B_), 256>>>((float*)d_out, idx, u);
}

// round 9
// speedup vs baseline: 5.6119x; 1.9207x over previous
#include <cuda_runtime.h>
#include <cuda_fp16.h>
#include <cstdint>

// Problem constants
#define B_  8
#define T_  4096
#define D_  1024
#define H_  16
#define DH_ 64
#define UMAX 44
#define MP_ 768     // padded M rows per batch (>= H*u = 656), multiple of 128

// ---------------- scratch (device globals; zero-initialized) ----------------
__device__ float  g_Xs [B_*UMAX*D_];
__device__ float  g_Qs [B_*UMAX*D_];
__device__ __half g_Qthi[(long)B_*MP_*D_];     // padded rows stay zero
__device__ __half g_Xhi [(long)B_*T_*D_];
__device__ __half g_XThi[(long)B_*D_*T_];      // x transposed [b][d][t]
__device__ float  g_S   [(long)B_*MP_*T_];     // scores (fp32)
__device__ __half g_Phi [(long)B_*MP_*T_];     // attn probs fp16 (padded rows zero)
__device__ float  g_AX  [(long)B_*MP_*D_];
__device__ float  g_ctx [B_*H_*UMAX*DH_];
__device__ float  g_mn  [B_*H_*DH_];
__device__ float  g_Y   [B_*(UMAX+1)*D_];
__device__ float  g_O   [B_*(UMAX+1)*D_];

// ================= helpers =================
__device__ __forceinline__ uint32_t smem_u32(const void* p) {
    uint32_t a;
    asm("{ .reg .u64 t; cvta.to.shared.u64 t, %1; cvt.u32.u64 %0, t; }" : "=r"(a) : "l"(p));
    return a;
}
__device__ __forceinline__ void ldsm4(uint32_t& r0, uint32_t& r1, uint32_t& r2, uint32_t& r3,
                                      uint32_t a) {
    asm volatile("ldmatrix.sync.aligned.m8n8.x4.shared.b16 {%0,%1,%2,%3}, [%4];"
                 : "=r"(r0), "=r"(r1), "=r"(r2), "=r"(r3) : "r"(a));
}
__device__ __forceinline__ void mma16816(float* d, const uint32_t* a, const uint32_t* b) {
    asm volatile("mma.sync.aligned.m16n8k16.row.col.f32.f16.f16.f32 "
                 "{%0,%1,%2,%3}, {%4,%5,%6,%7}, {%8,%9}, {%0,%1,%2,%3};"
                 : "+f"(d[0]), "+f"(d[1]), "+f"(d[2]), "+f"(d[3])
                 : "r"(a[0]), "r"(a[1]), "r"(a[2]), "r"(a[3]), "r"(b[0]), "r"(b[1]));
}
__device__ __forceinline__ void cp16(uint32_t s, const void* g) {
    asm volatile("cp.async.cg.shared.global [%0], [%1], 16;" :: "r"(s), "l"(g));
}
#define CP_COMMIT() asm volatile("cp.async.commit_group;" ::: "memory")
#define CP_WAIT0()  asm volatile("cp.async.wait_group 0;" ::: "memory")

// ================= plain-fp16 NT tensor-core GEMM (cp.async, SW128) =========
// C[b][m,n] = sum_k A[m,k]*B[n,k], fp32 accum. M,N mult of 128, K mult of 64.
#define BK 64
#define TILE_B (128 * BK * 2)   // 16384 bytes per tile
#define HG_SMEM (2 * 2 * TILE_B)  // 65536

__global__ void __launch_bounds__(256, 2)
hgemm(const __half* __restrict__ A, const __half* __restrict__ B,
      float* __restrict__ C, int K, int N, long sA, long sB, long sC)
{
    extern __shared__ char dsm[];
    const uint32_t sb = smem_u32(dsm);
    const int tid = threadIdx.x, lane = tid & 31, wid = tid >> 5;
    const int bz = blockIdx.z;
    const int m0 = blockIdx.y * 128, n0 = blockIdx.x * 128;
    const int wm = (wid & 3) * 32, wn = (wid >> 2) * 64;
    const __half* Ab = A + (long)bz * sA + (long)m0 * K;
    const __half* Bb = B + (long)bz * sB + (long)n0 * K;
    float* Cb = C + (long)bz * sC;

    float acc[2][8][4];
    #pragma unroll
    for (int i = 0; i < 2; i++)
        #pragma unroll
        for (int j = 0; j < 8; j++)
            #pragma unroll
            for (int q = 0; q < 4; q++) acc[i][j][q] = 0.f;

    const int fr = lane & 15, fc8 = lane >> 4;
    const int NCH = K / BK;

    auto issue = [&](int c) {
        const uint32_t base = sb + (uint32_t)(c & 1) * (2 * TILE_B);
        #pragma unroll
        for (int i = 0; i < 4; i++) {
            int idx = tid + i * 256;          // 0..1023
            int row = idx >> 3, cg = idx & 7;
            int phys = cg ^ (row & 7);        // SW128
            uint32_t off = (uint32_t)(row * 128 + phys * 16);
            const long gofs = (long)row * K + c * BK + cg * 8;
            cp16(base + off,          Ab + gofs);
            cp16(base + TILE_B + off, Bb + gofs);
        }
    };

    issue(0); CP_COMMIT();
    for (int c = 0; c < NCH; c++) {
        CP_WAIT0();
        __syncthreads();
        if (c + 1 < NCH) { issue(c + 1); CP_COMMIT(); }

        const uint32_t abase = sb + (uint32_t)(c & 1) * (2 * TILE_B);
        const uint32_t bbase = abase + TILE_B;
        #pragma unroll
        for (int kk = 0; kk < 4; kk++) {
            uint32_t a8[2][4], bh[8][2];
            const int cg = kk * 2 + fc8;
            #pragma unroll
            for (int mt = 0; mt < 2; mt++) {
                int row = wm + mt * 16 + fr;
                int phys = cg ^ (row & 7);
                ldsm4(a8[mt][0], a8[mt][1], a8[mt][2], a8[mt][3],
                      abase + row * 128 + phys * 16);
            }
            #pragma unroll
            for (int p = 0; p < 4; p++) {
                int row = wn + p * 16 + fr;
                int phys = cg ^ (row & 7);
                uint32_t r0, r1, r2, r3;
                ldsm4(r0, r1, r2, r3, bbase + row * 128 + phys * 16);
                bh[2*p][0] = r0; bh[2*p+1][0] = r1; bh[2*p][1] = r2; bh[2*p+1][1] = r3;
            }
            #pragma unroll
            for (int mt = 0; mt < 2; mt++)
                #pragma unroll
                for (int nt = 0; nt < 8; nt++)
                    mma16816(acc[mt][nt], a8[mt], bh[nt]);
        }
    }

    const int qr = lane >> 2, qc = (lane & 3) * 2;
    #pragma unroll
    for (int mt = 0; mt < 2; mt++)
        #pragma unroll
        for (int nt = 0; nt < 8; nt++) {
            long r = m0 + wm + mt * 16 + qr;
            int cc = n0 + wn + nt * 8 + qc;
            *reinterpret_cast<float2*>(&Cb[r * N + cc]) =
                make_float2(acc[mt][nt][0], acc[mt][nt][1]);
            *reinterpret_cast<float2*>(&Cb[(r + 8) * N + cc]) =
                make_float2(acc[mt][nt][2], acc[mt][nt][3]);
        }
}

// ================= batched 64x64-tile SIMT GEMM =================
template<bool NT, bool HALF_OUT>
__global__ void __launch_bounds__(256)
sgemm64(const float* __restrict__ A, const float* __restrict__ B, void* __restrict__ Cv,
        int M, int N, int K, int lda, int ldb, int ldc, int ZH,
        long sAb, long sAh, long sBb, long sBh, long sCb, long sCh,
        const float* __restrict__ bias, float alpha)
{
    const int zb = blockIdx.z / ZH, zh = blockIdx.z % ZH;
    A += (long)zb * sAb + (long)zh * sAh;
    B += (long)zb * sBb + (long)zh * sBh;
    const long coff = (long)zb * sCb + (long)zh * sCh;

    __shared__ float As[16][68];
    __shared__ float Bs[16][68];

    const int m0 = blockIdx.y * 64, n0 = blockIdx.x * 64;
    const int tid = threadIdx.x;
    const int lr = tid >> 2;
    const int lk = (tid & 3) * 4;
    const int bk = tid >> 4;
    const int bn = (tid & 15) * 4;
    const int tm = (tid >> 4) * 4, tn = (tid & 15) * 4;

    float acc[4][4];
    #pragma unroll
    for (int i = 0; i < 4; i++)
        #pragma unroll
        for (int j = 0; j < 4; j++) acc[i][j] = 0.f;

    for (int k0 = 0; k0 < K; k0 += 16) {
        {
            float4 v = make_float4(0.f, 0.f, 0.f, 0.f);
            int gm = m0 + lr;
            if (gm < M) v = *reinterpret_cast<const float4*>(A + (long)gm * lda + k0 + lk);
            As[lk + 0][lr] = v.x; As[lk + 1][lr] = v.y;
            As[lk + 2][lr] = v.z; As[lk + 3][lr] = v.w;
        }
        if (NT) {
            float4 v = *reinterpret_cast<const float4*>(B + (long)(n0 + lr) * ldb + k0 + lk);
            Bs[lk + 0][lr] = v.x; Bs[lk + 1][lr] = v.y;
            Bs[lk + 2][lr] = v.z; Bs[lk + 3][lr] = v.w;
        } else {
            float4 v = *reinterpret_cast<const float4*>(B + (long)(k0 + bk) * ldb + n0 + bn);
            *reinterpret_cast<float4*>(&Bs[bk][bn]) = v;
        }
        __syncthreads();

        #pragma unroll
        for (int kk = 0; kk < 16; kk++) {
            float ar[4], br[4];
            *reinterpret_cast<float4*>(ar) = *reinterpret_cast<const float4*>(&As[kk][tm]);
            *reinterpret_cast<float4*>(br) = *reinterpret_cast<const float4*>(&Bs[kk][tn]);
            #pragma unroll
            for (int i = 0; i < 4; i++)
                #pragma unroll
                for (int j = 0; j < 4; j++) acc[i][j] += ar[i] * br[j];
        }
        __syncthreads();
    }

    #pragma unroll
    for (int i = 0; i < 4; i++) {
        int gm = m0 + tm + i;
        if (gm >= M) break;
        #pragma unroll
        for (int j = 0; j < 4; j++) {
            int gn = n0 + tn + j;
            float v = acc[i][j] * alpha;
            if (bias) v += bias[gn];
            if (HALF_OUT)
                ((__half*)Cv)[coff + (long)gm * ldc + gn] = __float2half_rn(v);
            else
                ((float*)Cv)[coff + (long)gm * ldc + gn] = v;
        }
    }
}

// ---------------- small kernels ----------------
__global__ void conv_x_kernel(const float* __restrict__ x)
{
    long i = ((long)blockIdx.x * blockDim.x + threadIdx.x);
    long n4 = (long)B_ * T_ * D_ / 4;
    if (i >= n4) return;
    float4 v = reinterpret_cast<const float4*>(x)[i];
    __half h[4];
    h[0] = __float2half_rn(v.x); h[1] = __float2half_rn(v.y);
    h[2] = __float2half_rn(v.z); h[3] = __float2half_rn(v.w);
    *reinterpret_cast<uint2*>(&g_Xhi[i * 4]) = *reinterpret_cast<uint2*>(h);
}

__global__ void xT_conv_kernel(const float* __restrict__ x)
{
    __shared__ float tile[32][33];
    int b = blockIdx.z;
    int t0 = blockIdx.x * 32, d0 = blockIdx.y * 32;
    int tx = threadIdx.x, ty0 = threadIdx.y;   // 32 x 8
    #pragma unroll
    for (int j = 0; j < 4; j++) {
        int ty = ty0 + j * 8;
        tile[ty][tx] = x[((long)b * T_ + t0 + ty) * D_ + d0 + tx];
    }
    __syncthreads();
    #pragma unroll
    for (int j = 0; j < 4; j++) {
        int ty = ty0 + j * 8;
        float v = tile[tx][ty];   // = x[t0+tx][d0+ty]
        g_XThi[((long)b * D_ + d0 + ty) * T_ + t0 + tx] = __float2half_rn(v);
    }
}

__global__ void gather_kernel(const float* __restrict__ x, const int* __restrict__ idx, int u)
{
    int j = blockIdx.x, b = blockIdx.y;
    int t = idx[j];
    const float4* src = reinterpret_cast<const float4*>(x + ((long)b * T_ + t) * D_);
    float4* dst = reinterpret_cast<float4*>(g_Xs + ((long)b * u + j) * D_);
    dst[threadIdx.x] = src[threadIdx.x];
}

__global__ void softmax_kernel(int u)
{
    int MQ = H_ * u;
    int r = blockIdx.x % MQ, b = blockIdx.x / MQ;
    long row = (long)b * MP_ + r;
    const float* s = g_S + row * T_;
    __half* ph = g_Phi + row * T_;
    int tid = threadIdx.x;   // 256
    __shared__ float red[256];

    float mx = -1e30f;
    for (int t = tid; t < T_; t += 256) mx = fmaxf(mx, s[t]);
    red[tid] = mx; __syncthreads();
    for (int o = 128; o > 0; o >>= 1) { if (tid < o) red[tid] = fmaxf(red[tid], red[tid + o]); __syncthreads(); }
    mx = red[0]; __syncthreads();

    float sum = 0.f;
    for (int t = tid; t < T_; t += 256) sum += __expf(s[t] - mx);
    red[tid] = sum; __syncthreads();
    for (int o = 128; o > 0; o >>= 1) { if (tid < o) red[tid] += red[tid + o]; __syncthreads(); }
    float inv = 1.f / red[0];
    for (int t = tid; t < T_; t += 256)
        ph[t] = __float2half_rn(__expf(s[t] - mx) * inv);
}

__global__ void mean_kernel(int u)
{
    int h = blockIdx.x, b = blockIdx.y;
    int e = threadIdx.x;   // 64
    float s = 0.f;
    const float* base = g_ctx + (long)(b * H_ + h) * u * DH_ + e;
    for (int j = 0; j < u; j++) s += base[(long)j * DH_];
    g_mn[(b * H_ + h) * DH_ + e] = s / (float)u;
}

__global__ void yrows_kernel(int u)
{
    int r = blockIdx.x, b = blockIdx.y;
    int tid = threadIdx.x;   // 256
    float* out = g_Y + ((long)b * (u + 1) + r) * D_;
    #pragma unroll
    for (int q = 0; q < 4; q++) {
        int d = tid * 4 + q;
        int h = d >> 6, e = d & 63;
        float v = (r == 0) ? g_mn[(b * H_ + h) * DH_ + e]
                           : g_ctx[((long)(b * H_ + h) * u + (r - 1)) * DH_ + e];
        out[d] = v;
    }
}

__global__ void bcast_kernel(float4* __restrict__ out, const float* __restrict__ O, int u)
{
    long i = (long)blockIdx.x * blockDim.x + threadIdx.x;
    long total = (long)B_ * T_ * (D_ / 4);
    if (i >= total) return;
    int d4 = (int)(i & 255);
    long bt = i >> 8;
    int b = (int)(bt >> 12);
    out[i] = reinterpret_cast<const float4*>(O + (long)b * (u + 1) * D_)[d4];
}

__global__ void scatter_kernel(float* __restrict__ out, const int* __restrict__ idx, int u)
{
    int j = blockIdx.x, b = blockIdx.y;
    int t = idx[j];
    const float4* src = reinterpret_cast<const float4*>(g_O + ((long)b * (u + 1) + 1 + j) * D_);
    float4* dst = reinterpret_cast<float4*>(out + ((long)b * T_ + t) * D_);
    dst[threadIdx.x] = src[threadIdx.x];
}

// ---------------- host launch ----------------
template<typename Tp>
static Tp* symaddr_t(const void* sym)
{
    void* p = nullptr;
    cudaGetSymbolAddress(&p, sym);
    return (Tp*)p;
}

extern "C" void kernel_launch(void* const* d_in, const int* in_sizes, int n_in,
                              void* d_out, int out_size)
{
    const float* x  = (const float*)d_in[0];
    const float* Wq = (const float*)d_in[1];
    const float* Wk = (const float*)d_in[2];
    const float* Wv = (const float*)d_in[3];
    const float* Wo = (const float*)d_in[4];
    const float* bo = (const float*)d_in[5];
    const int*  idx = (const int*)d_in[6];
    const int u = in_sizes[6];            // 41

    cudaFuncSetAttribute(hgemm, cudaFuncAttributeMaxDynamicSharedMemorySize, HG_SMEM);

    float* Xs = symaddr_t<float>(g_Xs);
    float* Qs = symaddr_t<float>(g_Qs);
    float* S  = symaddr_t<float>(g_S);
    float* AX = symaddr_t<float>(g_AX);
    float* Y  = symaddr_t<float>(g_Y);
    float* O  = symaddr_t<float>(g_O);
    float* CT = symaddr_t<float>(g_ctx);
    __half* Qthi = symaddr_t<__half>(g_Qthi);
    __half* Xhi  = symaddr_t<__half>(g_Xhi);
    __half* XThi = symaddr_t<__half>(g_XThi);
    __half* Phi  = symaddr_t<__half>(g_Phi);

    const int MQ = H_ * u;                // 656

    // 1) gather query rows; fp16 conversions of x
    gather_kernel<<<dim3(u, B_), 256>>>(x, idx, u);
    {
        long n4 = (long)B_ * T_ * D_ / 4;
        conv_x_kernel<<<(unsigned)((n4 + 255) / 256), 256>>>(x);
    }
    xT_conv_kernel<<<dim3(T_ / 32, D_ / 32, B_), dim3(32, 8)>>>(x);

    // 2) Qs = Xs @ Wq^T  (M=B*u, N=D, K=D)
    sgemm64<true, false><<<dim3(D_ / 64, (B_ * u + 63) / 64, 1), 256>>>(
        Xs, Wq, Qs, B_ * u, D_, D_, D_, D_, D_, 1,
        0, 0, 0, 0, 0, 0, nullptr, 1.f);

    // 3) Qt_h = scale * Qs_h @ Wk_h  (batched over (b,h): M=u, N=D, K=DH) -> fp16
    sgemm64<false, true><<<dim3(D_ / 64, 1, B_ * H_), 256>>>(
        Qs, Wk, Qthi, u, D_, DH_, D_, D_, D_, H_,
        (long)u * D_, DH_, 0, (long)DH_ * D_, (long)MP_ * D_, (long)u * D_,
        nullptr, 0.125f);

    // 4) S[b] = Qt[b] @ x[b]^T  (fp16 mma: M=768, N=4096, K=1024)
    hgemm<<<dim3(T_ / 128, MP_ / 128, B_), 256, HG_SMEM>>>(
        Qthi, Xhi, S, D_, T_,
        (long)MP_ * D_, (long)T_ * D_, (long)MP_ * T_);

    // 5) softmax -> P fp16
    softmax_kernel<<<B_ * MQ, 256>>>(u);

    // 6) AX[b] = P[b] @ x[b] via NT with xT  (M=768, N=1024, K=4096)
    hgemm<<<dim3(D_ / 128, MP_ / 128, B_), 256, HG_SMEM>>>(
        Phi, XThi, AX, T_, D_,
        (long)MP_ * T_, (long)D_ * T_, (long)MP_ * D_);

    // 7) ctx_h = AX_h @ Wv_h^T  (batched over (b,h): M=u, N=DH, K=D)
    sgemm64<true, false><<<dim3(1, 1, B_ * H_), 256>>>(
        AX, Wv, CT, u, DH_, D_, D_, D_, DH_, H_,
        (long)MP_ * D_, (long)u * D_, 0, (long)DH_ * D_,
        (long)H_ * u * DH_, (long)u * DH_, nullptr, 1.f);

    // 8-9) mean, assemble rows
    mean_kernel<<<dim3(H_, B_), 64>>>(u);
    yrows_kernel<<<dim3(u + 1, B_), 256>>>(u);

    // 10) O = Y @ Wo^T + bo  (M=B*(u+1), N=D, K=D)
    sgemm64<true, false><<<dim3(D_ / 64, (B_ * (u + 1) + 63) / 64, 1), 256>>>(
        Y, Wo, O, B_ * (u + 1), D_, D_, D_, D_, D_, 1,
        0, 0, 0, 0, 0, 0, bo, 1.f);

    // 11-12) broadcast + scatter
    long total4 = (long)B_ * T_ * (D_ / 4);
    bcast_kernel<<<(unsigned)((total4 + 255) / 256), 256>>>((float4*)d_out, O, u);
    scatter_kernel<<<dim3(u, B_), 256>>>((float*)d_out, idx, u);
}

// round 10
// speedup vs baseline: 6.2497x; 1.1136x over previous
#include <cuda_runtime.h>
#include <cuda_fp16.h>
#include <cstdint>

// Problem constants
#define B_  8
#define T_  4096
#define D_  1024
#define H_  16
#define DH_ 64
#define UMAX 44
#define MP_ 768     // padded M rows per batch (>= H*u = 656), multiple of 128

// ---------------- scratch (device globals; zero-initialized) ----------------
__device__ float  g_Xs [B_*UMAX*D_];
__device__ float  g_Qs [B_*UMAX*D_];
__device__ __half g_Qthi[(long)B_*MP_*D_];     // padded rows stay zero
__device__ __half g_Xhi [(long)B_*T_*D_];
__device__ __half g_XThi[(long)B_*D_*T_];      // x transposed [b][d][t]
__device__ float  g_S   [(long)B_*MP_*T_];     // scores (fp32)
__device__ __half g_Phi [(long)B_*MP_*T_];     // attn probs fp16 (padded rows zero)
__device__ float  g_AX  [(long)B_*MP_*D_];
__device__ float  g_ctx [B_*H_*UMAX*DH_];
__device__ float  g_mn  [B_*H_*DH_];
__device__ float  g_Y   [B_*(UMAX+1)*D_];
__device__ float  g_O   [B_*(UMAX+1)*D_];

// ================= helpers =================
__device__ __forceinline__ uint32_t smem_u32(const void* p) {
    uint32_t a;
    asm("{ .reg .u64 t; cvta.to.shared.u64 t, %1; cvt.u32.u64 %0, t; }" : "=r"(a) : "l"(p));
    return a;
}
__device__ __forceinline__ void ldsm4(uint32_t& r0, uint32_t& r1, uint32_t& r2, uint32_t& r3,
                                      uint32_t a) {
    asm volatile("ldmatrix.sync.aligned.m8n8.x4.shared.b16 {%0,%1,%2,%3}, [%4];"
                 : "=r"(r0), "=r"(r1), "=r"(r2), "=r"(r3) : "r"(a));
}
__device__ __forceinline__ void mma16816(float* d, const uint32_t* a, const uint32_t* b) {
    asm volatile("mma.sync.aligned.m16n8k16.row.col.f32.f16.f16.f32 "
                 "{%0,%1,%2,%3}, {%4,%5,%6,%7}, {%8,%9}, {%0,%1,%2,%3};"
                 : "+f"(d[0]), "+f"(d[1]), "+f"(d[2]), "+f"(d[3])
                 : "r"(a[0]), "r"(a[1]), "r"(a[2]), "r"(a[3]), "r"(b[0]), "r"(b[1]));
}
__device__ __forceinline__ void cp16(uint32_t s, const void* g) {
    asm volatile("cp.async.cg.shared.global [%0], [%1], 16;" :: "r"(s), "l"(g));
}
#define CP_COMMIT() asm volatile("cp.async.commit_group;" ::: "memory")
#define CP_WAIT(n)  asm volatile("cp.async.wait_group %0;" :: "n"(n) : "memory")

// ================= plain-fp16 NT tensor-core GEMM (cp.async 3-stage, SW128) ==
// C[b][m,n] = sum_k A[m,k]*B[n,k], fp32 accum. M,N mult of 128, K mult of 64.
#define BK 64
#define TILE_B (128 * BK * 2)      // 16384 bytes per tile
#define HG_SMEM (3 * 2 * TILE_B)   // 98304 (3-stage)

__global__ void __launch_bounds__(256, 2)
hgemm(const __half* __restrict__ A, const __half* __restrict__ B,
      float* __restrict__ C, int K, int N, long sA, long sB, long sC)
{
    extern __shared__ char dsm[];
    const uint32_t sb = smem_u32(dsm);
    const int tid = threadIdx.x, lane = tid & 31, wid = tid >> 5;
    const int bz = blockIdx.z;
    const int m0 = blockIdx.y * 128, n0 = blockIdx.x * 128;
    const int wm = (wid & 3) * 32, wn = (wid >> 2) * 64;
    const __half* Ab = A + (long)bz * sA + (long)m0 * K;
    const __half* Bb = B + (long)bz * sB + (long)n0 * K;
    float* Cb = C + (long)bz * sC;

    float acc[2][8][4];
    #pragma unroll
    for (int i = 0; i < 2; i++)
        #pragma unroll
        for (int j = 0; j < 8; j++)
            #pragma unroll
            for (int q = 0; q < 4; q++) acc[i][j][q] = 0.f;

    const int fr = lane & 15, fc8 = lane >> 4;
    const int NCH = K / BK;

    auto issue = [&](int c) {
        const uint32_t base = sb + (uint32_t)(c % 3) * (2 * TILE_B);
        #pragma unroll
        for (int i = 0; i < 4; i++) {
            int idx = tid + i * 256;          // 0..1023
            int row = idx >> 3, cg = idx & 7;
            int phys = cg ^ (row & 7);        // SW128
            uint32_t off = (uint32_t)(row * 128 + phys * 16);
            const long gofs = (long)row * K + c * BK + cg * 8;
            cp16(base + off,          Ab + gofs);
            cp16(base + TILE_B + off, Bb + gofs);
        }
    };

    issue(0); CP_COMMIT();
    issue(1); CP_COMMIT();
    for (int c = 0; c < NCH; c++) {
        CP_WAIT(1);                 // group c done; group c+1 may still fly
        __syncthreads();
        if (c + 2 < NCH) { issue(c + 2); CP_COMMIT(); }

        const uint32_t abase = sb + (uint32_t)(c % 3) * (2 * TILE_B);
        const uint32_t bbase = abase + TILE_B;
        #pragma unroll
        for (int kk = 0; kk < 4; kk++) {
            uint32_t a8[2][4], bh[8][2];
            const int cg = kk * 2 + fc8;
            #pragma unroll
            for (int mt = 0; mt < 2; mt++) {
                int row = wm + mt * 16 + fr;
                int phys = cg ^ (row & 7);
                ldsm4(a8[mt][0], a8[mt][1], a8[mt][2], a8[mt][3],
                      abase + row * 128 + phys * 16);
            }
            #pragma unroll
            for (int p = 0; p < 4; p++) {
                int row = wn + p * 16 + fr;
                int phys = cg ^ (row & 7);
                uint32_t r0, r1, r2, r3;
                ldsm4(r0, r1, r2, r3, bbase + row * 128 + phys * 16);
                bh[2*p][0] = r0; bh[2*p+1][0] = r1; bh[2*p][1] = r2; bh[2*p+1][1] = r3;
            }
            #pragma unroll
            for (int mt = 0; mt < 2; mt++)
                #pragma unroll
                for (int nt = 0; nt < 8; nt++)
                    mma16816(acc[mt][nt], a8[mt], bh[nt]);
        }
    }

    const int qr = lane >> 2, qc = (lane & 3) * 2;
    #pragma unroll
    for (int mt = 0; mt < 2; mt++)
        #pragma unroll
        for (int nt = 0; nt < 8; nt++) {
            long r = m0 + wm + mt * 16 + qr;
            int cc = n0 + wn + nt * 8 + qc;
            *reinterpret_cast<float2*>(&Cb[r * N + cc]) =
                make_float2(acc[mt][nt][0], acc[mt][nt][1]);
            *reinterpret_cast<float2*>(&Cb[(r + 8) * N + cc]) =
                make_float2(acc[mt][nt][2], acc[mt][nt][3]);
        }
}

// ================= batched 64x64-tile SIMT GEMM with K-split =================
// blockIdx.z = ((zb*ZH)+zh)*ZK + zk ; each block does K/ZK; ZK>1 -> atomicAdd
// (C must be zeroed beforehand). Bias added by the zk==0 block.
template<bool NT, bool HALF_OUT>
__global__ void __launch_bounds__(256)
sgemm64(const float* __restrict__ A, const float* __restrict__ B, void* __restrict__ Cv,
        int M, int N, int K, int lda, int ldb, int ldc, int ZH, int ZK,
        long sAb, long sAh, long sBb, long sBh, long sCb, long sCh,
        const float* __restrict__ bias, float alpha)
{
    const int zk = blockIdx.z % ZK;
    const int zt = blockIdx.z / ZK;
    const int zb = zt / ZH, zh = zt % ZH;
    A += (long)zb * sAb + (long)zh * sAh;
    B += (long)zb * sBb + (long)zh * sBh;
    const long coff = (long)zb * sCb + (long)zh * sCh;

    __shared__ float As[16][68];
    __shared__ float Bs[16][68];

    const int m0 = blockIdx.y * 64, n0 = blockIdx.x * 64;
    const int tid = threadIdx.x;
    const int lr = tid >> 2;
    const int lk = (tid & 3) * 4;
    const int bk = tid >> 4;
    const int bn = (tid & 15) * 4;
    const int tm = (tid >> 4) * 4, tn = (tid & 15) * 4;

    float acc[4][4];
    #pragma unroll
    for (int i = 0; i < 4; i++)
        #pragma unroll
        for (int j = 0; j < 4; j++) acc[i][j] = 0.f;

    const int Kc = K / ZK;
    const int kbeg = zk * Kc, kend = kbeg + Kc;

    for (int k0 = kbeg; k0 < kend; k0 += 16) {
        {
            float4 v = make_float4(0.f, 0.f, 0.f, 0.f);
            int gm = m0 + lr;
            if (gm < M) v = *reinterpret_cast<const float4*>(A + (long)gm * lda + k0 + lk);
            As[lk + 0][lr] = v.x; As[lk + 1][lr] = v.y;
            As[lk + 2][lr] = v.z; As[lk + 3][lr] = v.w;
        }
        if (NT) {
            float4 v = *reinterpret_cast<const float4*>(B + (long)(n0 + lr) * ldb + k0 + lk);
            Bs[lk + 0][lr] = v.x; Bs[lk + 1][lr] = v.y;
            Bs[lk + 2][lr] = v.z; Bs[lk + 3][lr] = v.w;
        } else {
            float4 v = *reinterpret_cast<const float4*>(B + (long)(k0 + bk) * ldb + n0 + bn);
            *reinterpret_cast<float4*>(&Bs[bk][bn]) = v;
        }
        __syncthreads();

        #pragma unroll
        for (int kk = 0; kk < 16; kk++) {
            float ar[4], br[4];
            *reinterpret_cast<float4*>(ar) = *reinterpret_cast<const float4*>(&As[kk][tm]);
            *reinterpret_cast<float4*>(br) = *reinterpret_cast<const float4*>(&Bs[kk][tn]);
            #pragma unroll
            for (int i = 0; i < 4; i++)
                #pragma unroll
                for (int j = 0; j < 4; j++) acc[i][j] += ar[i] * br[j];
        }
        __syncthreads();
    }

    #pragma unroll
    for (int i = 0; i < 4; i++) {
        int gm = m0 + tm + i;
        if (gm >= M) break;
        #pragma unroll
        for (int j = 0; j < 4; j++) {
            int gn = n0 + tn + j;
            float v = acc[i][j] * alpha;
            if (bias && zk == 0) v += bias[gn];
            if (HALF_OUT) {
                ((__half*)Cv)[coff + (long)gm * ldc + gn] = __float2half_rn(v);
            } else if (ZK > 1) {
                atomicAdd(&((float*)Cv)[coff + (long)gm * ldc + gn], v);
            } else {
                ((float*)Cv)[coff + (long)gm * ldc + gn] = v;
            }
        }
    }
}

// ---------------- small kernels ----------------
__global__ void zero_kernel(float4* __restrict__ p, long n4)
{
    long i = (long)blockIdx.x * blockDim.x + threadIdx.x;
    if (i < n4) p[i] = make_float4(0.f, 0.f, 0.f, 0.f);
}

__global__ void conv_x_kernel(const float* __restrict__ x)
{
    long i = ((long)blockIdx.x * blockDim.x + threadIdx.x);
    long n4 = (long)B_ * T_ * D_ / 4;
    if (i >= n4) return;
    float4 v = reinterpret_cast<const float4*>(x)[i];
    __half h[4];
    h[0] = __float2half_rn(v.x); h[1] = __float2half_rn(v.y);
    h[2] = __float2half_rn(v.z); h[3] = __float2half_rn(v.w);
    *reinterpret_cast<uint2*>(&g_Xhi[i * 4]) = *reinterpret_cast<uint2*>(h);
}

__global__ void xT_conv_kernel(const float* __restrict__ x)
{
    __shared__ float tile[32][33];
    int b = blockIdx.z;
    int t0 = blockIdx.x * 32, d0 = blockIdx.y * 32;
    int tx = threadIdx.x, ty0 = threadIdx.y;   // 32 x 8
    #pragma unroll
    for (int j = 0; j < 4; j++) {
        int ty = ty0 + j * 8;
        tile[ty][tx] = x[((long)b * T_ + t0 + ty) * D_ + d0 + tx];
    }
    __syncthreads();
    #pragma unroll
    for (int j = 0; j < 4; j++) {
        int ty = ty0 + j * 8;
        float v = tile[tx][ty];   // = x[t0+tx][d0+ty]
        g_XThi[((long)b * D_ + d0 + ty) * T_ + t0 + tx] = __float2half_rn(v);
    }
}

__global__ void gather_kernel(const float* __restrict__ x, const int* __restrict__ idx, int u)
{
    int j = blockIdx.x, b = blockIdx.y;
    int t = idx[j];
    const float4* src = reinterpret_cast<const float4*>(x + ((long)b * T_ + t) * D_);
    float4* dst = reinterpret_cast<float4*>(g_Xs + ((long)b * u + j) * D_);
    dst[threadIdx.x] = src[threadIdx.x];
}

__global__ void softmax_kernel(int u)
{
    int MQ = H_ * u;
    int r = blockIdx.x % MQ, b = blockIdx.x / MQ;
    long row = (long)b * MP_ + r;
    const float* s = g_S + row * T_;
    __half* ph = g_Phi + row * T_;
    int tid = threadIdx.x;   // 256
    __shared__ float red[256];

    float mx = -1e30f;
    for (int t = tid; t < T_; t += 256) mx = fmaxf(mx, s[t]);
    red[tid] = mx; __syncthreads();
    for (int o = 128; o > 0; o >>= 1) { if (tid < o) red[tid] = fmaxf(red[tid], red[tid + o]); __syncthreads(); }
    mx = red[0]; __syncthreads();

    float sum = 0.f;
    for (int t = tid; t < T_; t += 256) sum += __expf(s[t] - mx);
    red[tid] = sum; __syncthreads();
    for (int o = 128; o > 0; o >>= 1) { if (tid < o) red[tid] += red[tid + o]; __syncthreads(); }
    float inv = 1.f / red[0];
    for (int t = tid; t < T_; t += 256)
        ph[t] = __float2half_rn(__expf(s[t] - mx) * inv);
}

__global__ void mean_kernel(int u)
{
    int h = blockIdx.x, b = blockIdx.y;
    int e = threadIdx.x;   // 64
    float s = 0.f;
    const float* base = g_ctx + (long)(b * H_ + h) * u * DH_ + e;
    for (int j = 0; j < u; j++) s += base[(long)j * DH_];
    g_mn[(b * H_ + h) * DH_ + e] = s / (float)u;
}

__global__ void yrows_kernel(int u)
{
    int r = blockIdx.x, b = blockIdx.y;
    int tid = threadIdx.x;   // 256
    float* out = g_Y + ((long)b * (u + 1) + r) * D_;
    #pragma unroll
    for (int q = 0; q < 4; q++) {
        int d = tid * 4 + q;
        int h = d >> 6, e = d & 63;
        float v = (r == 0) ? g_mn[(b * H_ + h) * DH_ + e]
                           : g_ctx[((long)(b * H_ + h) * u + (r - 1)) * DH_ + e];
        out[d] = v;
    }
}

__global__ void bcast_kernel(float4* __restrict__ out, const float* __restrict__ O, int u)
{
    long i = (long)blockIdx.x * blockDim.x + threadIdx.x;
    long total = (long)B_ * T_ * (D_ / 4);
    if (i >= total) return;
    int d4 = (int)(i & 255);
    long bt = i >> 8;
    int b = (int)(bt >> 12);
    out[i] = reinterpret_cast<const float4*>(O + (long)b * (u + 1) * D_)[d4];
}

__global__ void scatter_kernel(float* __restrict__ out, const int* __restrict__ idx, int u)
{
    int j = blockIdx.x, b = blockIdx.y;
    int t = idx[j];
    const float4* src = reinterpret_cast<const float4*>(g_O + ((long)b * (u + 1) + 1 + j) * D_);
    float4* dst = reinterpret_cast<float4*>(out + ((long)b * T_ + t) * D_);
    dst[threadIdx.x] = src[threadIdx.x];
}

// ---------------- host launch ----------------
template<typename Tp>
static Tp* symaddr_t(const void* sym)
{
    void* p = nullptr;
    cudaGetSymbolAddress(&p, sym);
    return (Tp*)p;
}

extern "C" void kernel_launch(void* const* d_in, const int* in_sizes, int n_in,
                              void* d_out, int out_size)
{
    const float* x  = (const float*)d_in[0];
    const float* Wq = (const float*)d_in[1];
    const float* Wk = (const float*)d_in[2];
    const float* Wv = (const float*)d_in[3];
    const float* Wo = (const float*)d_in[4];
    const float* bo = (const float*)d_in[5];
    const int*  idx = (const int*)d_in[6];
    const int u = in_sizes[6];            // 41

    cudaFuncSetAttribute(hgemm, cudaFuncAttributeMaxDynamicSharedMemorySize, HG_SMEM);

    float* Xs = symaddr_t<float>(g_Xs);
    float* Qs = symaddr_t<float>(g_Qs);
    float* S  = symaddr_t<float>(g_S);
    float* AX = symaddr_t<float>(g_AX);
    float* Y  = symaddr_t<float>(g_Y);
    float* O  = symaddr_t<float>(g_O);
    float* CT = symaddr_t<float>(g_ctx);
    __half* Qthi = symaddr_t<__half>(g_Qthi);
    __half* Xhi  = symaddr_t<__half>(g_Xhi);
    __half* XThi = symaddr_t<__half>(g_XThi);
    __half* Phi  = symaddr_t<__half>(g_Phi);

    const int MQ = H_ * u;                // 656
    const int KS = 4;                     // K-split factor for starved gemms

    // 0) zero atomic-accumulation targets
    zero_kernel<<<(B_*UMAX*D_/4 + 255)/256, 256>>>((float4*)Qs, B_*UMAX*D_/4);
    zero_kernel<<<(B_*H_*UMAX*DH_/4 + 255)/256, 256>>>((float4*)CT, B_*H_*UMAX*DH_/4);
    zero_kernel<<<(B_*(UMAX+1)*D_/4 + 255)/256, 256>>>((float4*)O, B_*(UMAX+1)*D_/4);

    // 1) gather query rows; fp16 conversions of x
    gather_kernel<<<dim3(u, B_), 256>>>(x, idx, u);
    {
        long n4 = (long)B_ * T_ * D_ / 4;
        conv_x_kernel<<<(unsigned)((n4 + 255) / 256), 256>>>(x);
    }
    xT_conv_kernel<<<dim3(T_ / 32, D_ / 32, B_), dim3(32, 8)>>>(x);

    // 2) Qs = Xs @ Wq^T  (M=B*u, N=D, K=D; K-split x4)
    sgemm64<true, false><<<dim3(D_ / 64, (B_ * u + 63) / 64, KS), 256>>>(
        Xs, Wq, Qs, B_ * u, D_, D_, D_, D_, D_, 1, KS,
        0, 0, 0, 0, 0, 0, nullptr, 1.f);

    // 3) Qt_h = scale * Qs_h @ Wk_h  (batched over (b,h): M=u, N=D, K=DH) -> fp16
    sgemm64<false, true><<<dim3(D_ / 64, 1, B_ * H_), 256>>>(
        Qs, Wk, Qthi, u, D_, DH_, D_, D_, D_, H_, 1,
        (long)u * D_, DH_, 0, (long)DH_ * D_, (long)MP_ * D_, (long)u * D_,
        nullptr, 0.125f);

    // 4) S[b] = Qt[b] @ x[b]^T  (fp16 mma: M=768, N=4096, K=1024)
    hgemm<<<dim3(T_ / 128, MP_ / 128, B_), 256, HG_SMEM>>>(
        Qthi, Xhi, S, D_, T_,
        (long)MP_ * D_, (long)T_ * D_, (long)MP_ * T_);

    // 5) softmax -> P fp16
    softmax_kernel<<<B_ * MQ, 256>>>(u);

    // 6) AX[b] = P[b] @ x[b] via NT with xT  (M=768, N=1024, K=4096)
    hgemm<<<dim3(D_ / 128, MP_ / 128, B_), 256, HG_SMEM>>>(
        Phi, XThi, AX, T_, D_,
        (long)MP_ * T_, (long)D_ * T_, (long)MP_ * D_);

    // 7) ctx_h = AX_h @ Wv_h^T  (batched over (b,h): M=u, N=DH, K=D; K-split x4)
    sgemm64<true, false><<<dim3(1, 1, B_ * H_ * KS), 256>>>(
        AX, Wv, CT, u, DH_, D_, D_, D_, DH_, H_, KS,
        (long)MP_ * D_, (long)u * D_, 0, (long)DH_ * D_,
        (long)H_ * u * DH_, (long)u * DH_, nullptr, 1.f);

    // 8-9) mean, assemble rows
    mean_kernel<<<dim3(H_, B_), 64>>>(u);
    yrows_kernel<<<dim3(u + 1, B_), 256>>>(u);

    // 10) O = Y @ Wo^T + bo  (M=B*(u+1), N=D, K=D; K-split x4)
    sgemm64<true, false><<<dim3(D_ / 64, (B_ * (u + 1) + 63) / 64, KS), 256>>>(
        Y, Wo, O, B_ * (u + 1), D_, D_, D_, D_, D_, 1, KS,
        0, 0, 0, 0, 0, 0, bo, 1.f);

    // 11-12) broadcast + scatter
    long total4 = (long)B_ * T_ * (D_ / 4);
    bcast_kernel<<<(unsigned)((total4 + 255) / 256), 256>>>((float4*)d_out, O, u);
    scatter_kernel<<<dim3(u, B_), 256>>>((float*)d_out, idx, u);
}

// round 11
// speedup vs baseline: 6.5035x; 1.0406x over previous
#include <cuda_runtime.h>
#include <cuda_fp16.h>
#include <cstdint>

// Problem constants
#define B_  8
#define T_  4096
#define D_  1024
#define H_  16
#define DH_ 64
#define UMAX 44
#define MP_ 768     // padded M rows per batch (>= H*u = 656), multiple of 128

// ---------------- scratch (device globals; zero-initialized) ----------------
__device__ float  g_Xs [B_*UMAX*D_];
__device__ float  g_Qs [B_*UMAX*D_];
__device__ __half g_Qthi[(long)B_*MP_*D_];     // padded rows stay zero
__device__ __half g_Xhi [(long)B_*T_*D_];
__device__ float  g_S   [(long)B_*MP_*T_];     // scores (fp32)
__device__ __half g_Phi [(long)B_*MP_*T_];     // attn probs fp16 (padded rows zero)
__device__ float  g_AX  [(long)B_*MP_*D_];
__device__ float  g_ctx [B_*H_*UMAX*DH_];
__device__ float  g_mn  [B_*H_*DH_];
__device__ float  g_Y   [B_*(UMAX+1)*D_];
__device__ float  g_O   [B_*(UMAX+1)*D_];

// ================= helpers =================
__device__ __forceinline__ uint32_t smem_u32(const void* p) {
    uint32_t a;
    asm("{ .reg .u64 t; cvta.to.shared.u64 t, %1; cvt.u32.u64 %0, t; }" : "=r"(a) : "l"(p));
    return a;
}
__device__ __forceinline__ void ldsm4(uint32_t& r0, uint32_t& r1, uint32_t& r2, uint32_t& r3,
                                      uint32_t a) {
    asm volatile("ldmatrix.sync.aligned.m8n8.x4.shared.b16 {%0,%1,%2,%3}, [%4];"
                 : "=r"(r0), "=r"(r1), "=r"(r2), "=r"(r3) : "r"(a));
}
__device__ __forceinline__ void ldsm4t(uint32_t& r0, uint32_t& r1, uint32_t& r2, uint32_t& r3,
                                       uint32_t a) {
    asm volatile("ldmatrix.sync.aligned.m8n8.x4.trans.shared.b16 {%0,%1,%2,%3}, [%4];"
                 : "=r"(r0), "=r"(r1), "=r"(r2), "=r"(r3) : "r"(a));
}
__device__ __forceinline__ void mma16816(float* d, const uint32_t* a, const uint32_t* b) {
    asm volatile("mma.sync.aligned.m16n8k16.row.col.f32.f16.f16.f32 "
                 "{%0,%1,%2,%3}, {%4,%5,%6,%7}, {%8,%9}, {%0,%1,%2,%3};"
                 : "+f"(d[0]), "+f"(d[1]), "+f"(d[2]), "+f"(d[3])
                 : "r"(a[0]), "r"(a[1]), "r"(a[2]), "r"(a[3]), "r"(b[0]), "r"(b[1]));
}
__device__ __forceinline__ void cp16(uint32_t s, const void* g) {
    asm volatile("cp.async.cg.shared.global [%0], [%1], 16;" :: "r"(s), "l"(g));
}
#define CP_COMMIT() asm volatile("cp.async.commit_group;" ::: "memory")
#define CP_WAIT(n)  asm volatile("cp.async.wait_group %0;" :: "n"(n) : "memory")

// ================= fp16 tensor-core GEMM (cp.async 3-stage, SW128) ==========
// NT: C[m,n] = sum_k A[m,k]*B[n,k]  (B row-major [N][K], ldb = K)
// NN: C[m,n] = sum_k A[m,k]*B[k,n]  (B row-major [K][N], ldb = ldbB)
// fp32 accum. M,N mult of 128, K mult of 64.
#define BK 64
#define TILE_B (128 * BK * 2)      // 16384 bytes per tile
#define HG_SMEM (3 * 2 * TILE_B)   // 98304 (3-stage)

template<bool NT>
__global__ void __launch_bounds__(256, 2)
hgemm(const __half* __restrict__ A, const __half* __restrict__ B,
      float* __restrict__ C, int K, int N, int ldbB, long sA, long sB, long sC)
{
    extern __shared__ char dsm[];
    const uint32_t sb = smem_u32(dsm);
    const int tid = threadIdx.x, lane = tid & 31, wid = tid >> 5;
    const int bz = blockIdx.z;
    const int m0 = blockIdx.y * 128, n0 = blockIdx.x * 128;
    const int wm = (wid & 3) * 32, wn = (wid >> 2) * 64;
    const __half* Ab = A + (long)bz * sA + (long)m0 * K;
    const __half* Bb = NT ? (B + (long)bz * sB + (long)n0 * K)
                          : (B + (long)bz * sB + n0);
    float* Cb = C + (long)bz * sC;

    float acc[2][8][4];
    #pragma unroll
    for (int i = 0; i < 2; i++)
        #pragma unroll
        for (int j = 0; j < 8; j++)
            #pragma unroll
            for (int q = 0; q < 4; q++) acc[i][j][q] = 0.f;

    const int fr = lane & 15, fc8 = lane >> 4;
    const int NCH = K / BK;

    auto issue = [&](int c) {
        const uint32_t base = sb + (uint32_t)(c % 3) * (2 * TILE_B);
        // A tile: 128 rows x 64 halves (128B rows, 8 chunks)
        #pragma unroll
        for (int i = 0; i < 4; i++) {
            int idx = tid + i * 256;          // 0..1023
            int row = idx >> 3, cg = idx & 7;
            int phys = cg ^ (row & 7);
            cp16(base + (uint32_t)(row * 128 + phys * 16),
                 Ab + (long)row * K + c * BK + cg * 8);
        }
        if (NT) {
            // B tile: 128 n-rows x 64 k-halves (128B rows)
            #pragma unroll
            for (int i = 0; i < 4; i++) {
                int idx = tid + i * 256;
                int row = idx >> 3, cg = idx & 7;
                int phys = cg ^ (row & 7);
                cp16(base + TILE_B + (uint32_t)(row * 128 + phys * 16),
                     Bb + (long)row * K + c * BK + cg * 8);
            }
        } else {
            // B tile: 64 k-rows x 128 n-halves (256B rows, 16 chunks)
            #pragma unroll
            for (int i = 0; i < 4; i++) {
                int idx = tid + i * 256;
                int row = idx >> 4, cg = idx & 15;
                int phys = cg ^ (row & 7);
                cp16(base + TILE_B + (uint32_t)(row * 256 + phys * 16),
                     Bb + (long)(c * BK + row) * ldbB + cg * 8);
            }
        }
    };

    issue(0); CP_COMMIT();
    issue(1); CP_COMMIT();
    for (int c = 0; c < NCH; c++) {
        CP_WAIT(1);
        __syncthreads();
        if (c + 2 < NCH) { issue(c + 2); CP_COMMIT(); }

        const uint32_t abase = sb + (uint32_t)(c % 3) * (2 * TILE_B);
        const uint32_t bbase = abase + TILE_B;
        #pragma unroll
        for (int kk = 0; kk < 4; kk++) {
            uint32_t a8[2][4], bh[8][2];
            #pragma unroll
            for (int mt = 0; mt < 2; mt++) {
                int row = wm + mt * 16 + fr;
                int cg = kk * 2 + fc8;
                int phys = cg ^ (row & 7);
                ldsm4(a8[mt][0], a8[mt][1], a8[mt][2], a8[mt][3],
                      abase + row * 128 + phys * 16);
            }
            #pragma unroll
            for (int p = 0; p < 4; p++) {
                uint32_t r0, r1, r2, r3;
                if (NT) {
                    int row = wn + p * 16 + fr;
                    int cg = kk * 2 + fc8;
                    int phys = cg ^ (row & 7);
                    ldsm4(r0, r1, r2, r3, bbase + row * 128 + phys * 16);
                } else {
                    int g = lane >> 3, j = lane & 7;
                    int krow = kk * 16 + ((g >> 1) << 3) + j;
                    int nchunk = ((wn + p * 16) >> 3) + (g & 1);
                    int phys = nchunk ^ (krow & 7);
                    ldsm4t(r0, r1, r2, r3, bbase + krow * 256 + phys * 16);
                }
                bh[2*p][0] = r0; bh[2*p+1][0] = r1; bh[2*p][1] = r2; bh[2*p+1][1] = r3;
            }
            #pragma unroll
            for (int mt = 0; mt < 2; mt++)
                #pragma unroll
                for (int nt = 0; nt < 8; nt++)
                    mma16816(acc[mt][nt], a8[mt], bh[nt]);
        }
    }

    const int qr = lane >> 2, qc = (lane & 3) * 2;
    #pragma unroll
    for (int mt = 0; mt < 2; mt++)
        #pragma unroll
        for (int nt = 0; nt < 8; nt++) {
            long r = m0 + wm + mt * 16 + qr;
            int cc = n0 + wn + nt * 8 + qc;
            *reinterpret_cast<float2*>(&Cb[r * N + cc]) =
                make_float2(acc[mt][nt][0], acc[mt][nt][1]);
            *reinterpret_cast<float2*>(&Cb[(r + 8) * N + cc]) =
                make_float2(acc[mt][nt][2], acc[mt][nt][3]);
        }
}

// ================= batched 64x64-tile SIMT GEMM with K-split =================
template<bool NT, bool HALF_OUT>
__global__ void __launch_bounds__(256)
sgemm64(const float* __restrict__ A, const float* __restrict__ B, void* __restrict__ Cv,
        int M, int N, int K, int lda, int ldb, int ldc, int ZH, int ZK,
        long sAb, long sAh, long sBb, long sBh, long sCb, long sCh,
        const float* __restrict__ bias, float alpha)
{
    const int zk = blockIdx.z % ZK;
    const int zt = blockIdx.z / ZK;
    const int zb = zt / ZH, zh = zt % ZH;
    A += (long)zb * sAb + (long)zh * sAh;
    B += (long)zb * sBb + (long)zh * sBh;
    const long coff = (long)zb * sCb + (long)zh * sCh;

    __shared__ float As[16][68];
    __shared__ float Bs[16][68];

    const int m0 = blockIdx.y * 64, n0 = blockIdx.x * 64;
    const int tid = threadIdx.x;
    const int lr = tid >> 2;
    const int lk = (tid & 3) * 4;
    const int bk = tid >> 4;
    const int bn = (tid & 15) * 4;
    const int tm = (tid >> 4) * 4, tn = (tid & 15) * 4;

    float acc[4][4];
    #pragma unroll
    for (int i = 0; i < 4; i++)
        #pragma unroll
        for (int j = 0; j < 4; j++) acc[i][j] = 0.f;

    const int Kc = K / ZK;
    const int kbeg = zk * Kc, kend = kbeg + Kc;

    for (int k0 = kbeg; k0 < kend; k0 += 16) {
        {
            float4 v = make_float4(0.f, 0.f, 0.f, 0.f);
            int gm = m0 + lr;
            if (gm < M) v = *reinterpret_cast<const float4*>(A + (long)gm * lda + k0 + lk);
            As[lk + 0][lr] = v.x; As[lk + 1][lr] = v.y;
            As[lk + 2][lr] = v.z; As[lk + 3][lr] = v.w;
        }
        if (NT) {
            float4 v = *reinterpret_cast<const float4*>(B + (long)(n0 + lr) * ldb + k0 + lk);
            Bs[lk + 0][lr] = v.x; Bs[lk + 1][lr] = v.y;
            Bs[lk + 2][lr] = v.z; Bs[lk + 3][lr] = v.w;
        } else {
            float4 v = *reinterpret_cast<const float4*>(B + (long)(k0 + bk) * ldb + n0 + bn);
            *reinterpret_cast<float4*>(&Bs[bk][bn]) = v;
        }
        __syncthreads();

        #pragma unroll
        for (int kk = 0; kk < 16; kk++) {
            float ar[4], br[4];
            *reinterpret_cast<float4*>(ar) = *reinterpret_cast<const float4*>(&As[kk][tm]);
            *reinterpret_cast<float4*>(br) = *reinterpret_cast<const float4*>(&Bs[kk][tn]);
            #pragma unroll
            for (int i = 0; i < 4; i++)
                #pragma unroll
                for (int j = 0; j < 4; j++) acc[i][j] += ar[i] * br[j];
        }
        __syncthreads();
    }

    #pragma unroll
    for (int i = 0; i < 4; i++) {
        int gm = m0 + tm + i;
        if (gm >= M) break;
        #pragma unroll
        for (int j = 0; j < 4; j++) {
            int gn = n0 + tn + j;
            float v = acc[i][j] * alpha;
            if (bias && zk == 0) v += bias[gn];
            if (HALF_OUT) {
                ((__half*)Cv)[coff + (long)gm * ldc + gn] = __float2half_rn(v);
            } else if (ZK > 1) {
                atomicAdd(&((float*)Cv)[coff + (long)gm * ldc + gn], v);
            } else {
                ((float*)Cv)[coff + (long)gm * ldc + gn] = v;
            }
        }
    }
}

// ---------------- small kernels ----------------
__global__ void zero_kernel(float4* __restrict__ p, long n4)
{
    long i = (long)blockIdx.x * blockDim.x + threadIdx.x;
    if (i < n4) p[i] = make_float4(0.f, 0.f, 0.f, 0.f);
}

__global__ void conv_x_kernel(const float* __restrict__ x)
{
    long i = ((long)blockIdx.x * blockDim.x + threadIdx.x);
    long n4 = (long)B_ * T_ * D_ / 4;
    if (i >= n4) return;
    float4 v = reinterpret_cast<const float4*>(x)[i];
    __half h[4];
    h[0] = __float2half_rn(v.x); h[1] = __float2half_rn(v.y);
    h[2] = __float2half_rn(v.z); h[3] = __float2half_rn(v.w);
    *reinterpret_cast<uint2*>(&g_Xhi[i * 4]) = *reinterpret_cast<uint2*>(h);
}

__global__ void gather_kernel(const float* __restrict__ x, const int* __restrict__ idx, int u)
{
    int j = blockIdx.x, b = blockIdx.y;
    int t = idx[j];
    const float4* src = reinterpret_cast<const float4*>(x + ((long)b * T_ + t) * D_);
    float4* dst = reinterpret_cast<float4*>(g_Xs + ((long)b * u + j) * D_);
    dst[threadIdx.x] = src[threadIdx.x];
}

__global__ void softmax_kernel(int u)
{
    int MQ = H_ * u;
    int r = blockIdx.x % MQ, b = blockIdx.x / MQ;
    long row = (long)b * MP_ + r;
    const float* s = g_S + row * T_;
    __half* ph = g_Phi + row * T_;
    int tid = threadIdx.x;   // 256
    __shared__ float red[256];

    float mx = -1e30f;
    for (int t = tid; t < T_; t += 256) mx = fmaxf(mx, s[t]);
    red[tid] = mx; __syncthreads();
    for (int o = 128; o > 0; o >>= 1) { if (tid < o) red[tid] = fmaxf(red[tid], red[tid + o]); __syncthreads(); }
    mx = red[0]; __syncthreads();

    float sum = 0.f;
    for (int t = tid; t < T_; t += 256) sum += __expf(s[t] - mx);
    red[tid] = sum; __syncthreads();
    for (int o = 128; o > 0; o >>= 1) { if (tid < o) red[tid] += red[tid + o]; __syncthreads(); }
    float inv = 1.f / red[0];
    for (int t = tid; t < T_; t += 256)
        ph[t] = __float2half_rn(__expf(s[t] - mx) * inv);
}

__global__ void mean_kernel(int u)
{
    int h = blockIdx.x, b = blockIdx.y;
    int e = threadIdx.x;   // 64
    float s = 0.f;
    const float* base = g_ctx + (long)(b * H_ + h) * u * DH_ + e;
    for (int j = 0; j < u; j++) s += base[(long)j * DH_];
    g_mn[(b * H_ + h) * DH_ + e] = s / (float)u;
}

__global__ void yrows_kernel(int u)
{
    int r = blockIdx.x, b = blockIdx.y;
    int tid = threadIdx.x;   // 256
    float* out = g_Y + ((long)b * (u + 1) + r) * D_;
    #pragma unroll
    for (int q = 0; q < 4; q++) {
        int d = tid * 4 + q;
        int h = d >> 6, e = d & 63;
        float v = (r == 0) ? g_mn[(b * H_ + h) * DH_ + e]
                           : g_ctx[((long)(b * H_ + h) * u + (r - 1)) * DH_ + e];
        out[d] = v;
    }
}

__global__ void bcast_kernel(float4* __restrict__ out, const float* __restrict__ O, int u)
{
    long i = (long)blockIdx.x * blockDim.x + threadIdx.x;
    long total = (long)B_ * T_ * (D_ / 4);
    if (i >= total) return;
    int d4 = (int)(i & 255);
    long bt = i >> 8;
    int b = (int)(bt >> 12);
    out[i] = reinterpret_cast<const float4*>(O + (long)b * (u + 1) * D_)[d4];
}

__global__ void scatter_kernel(float* __restrict__ out, const int* __restrict__ idx, int u)
{
    int j = blockIdx.x, b = blockIdx.y;
    int t = idx[j];
    const float4* src = reinterpret_cast<const float4*>(g_O + ((long)b * (u + 1) + 1 + j) * D_);
    float4* dst = reinterpret_cast<float4*>(out + ((long)b * T_ + t) * D_);
    dst[threadIdx.x] = src[threadIdx.x];
}

// ---------------- host launch ----------------
template<typename Tp>
static Tp* symaddr_t(const void* sym)
{
    void* p = nullptr;
    cudaGetSymbolAddress(&p, sym);
    return (Tp*)p;
}

extern "C" void kernel_launch(void* const* d_in, const int* in_sizes, int n_in,
                              void* d_out, int out_size)
{
    const float* x  = (const float*)d_in[0];
    const float* Wq = (const float*)d_in[1];
    const float* Wk = (const float*)d_in[2];
    const float* Wv = (const float*)d_in[3];
    const float* Wo = (const float*)d_in[4];
    const float* bo = (const float*)d_in[5];
    const int*  idx = (const int*)d_in[6];
    const int u = in_sizes[6];            // 41

    cudaFuncSetAttribute(hgemm<true>,  cudaFuncAttributeMaxDynamicSharedMemorySize, HG_SMEM);
    cudaFuncSetAttribute(hgemm<false>, cudaFuncAttributeMaxDynamicSharedMemorySize, HG_SMEM);

    float* Xs = symaddr_t<float>(g_Xs);
    float* Qs = symaddr_t<float>(g_Qs);
    float* S  = symaddr_t<float>(g_S);
    float* AX = symaddr_t<float>(g_AX);
    float* Y  = symaddr_t<float>(g_Y);
    float* O  = symaddr_t<float>(g_O);
    float* CT = symaddr_t<float>(g_ctx);
    __half* Qthi = symaddr_t<__half>(g_Qthi);
    __half* Xhi  = symaddr_t<__half>(g_Xhi);
    __half* Phi  = symaddr_t<__half>(g_Phi);

    const int MQ = H_ * u;                // 656
    const int KS = 4;                     // K-split factor for starved gemms

    // 0) zero atomic-accumulation targets
    zero_kernel<<<(B_*UMAX*D_/4 + 255)/256, 256>>>((float4*)Qs, B_*UMAX*D_/4);
    zero_kernel<<<(B_*H_*UMAX*DH_/4 + 255)/256, 256>>>((float4*)CT, B_*H_*UMAX*DH_/4);
    zero_kernel<<<(B_*(UMAX+1)*D_/4 + 255)/256, 256>>>((float4*)O, B_*(UMAX+1)*D_/4);

    // 1) gather query rows; fp16 conversion of x
    gather_kernel<<<dim3(u, B_), 256>>>(x, idx, u);
    {
        long n4 = (long)B_ * T_ * D_ / 4;
        conv_x_kernel<<<(unsigned)((n4 + 255) / 256), 256>>>(x);
    }

    // 2) Qs = Xs @ Wq^T  (M=B*u, N=D, K=D; K-split x4)
    sgemm64<true, false><<<dim3(D_ / 64, (B_ * u + 63) / 64, KS), 256>>>(
        Xs, Wq, Qs, B_ * u, D_, D_, D_, D_, D_, 1, KS,
        0, 0, 0, 0, 0, 0, nullptr, 1.f);

    // 3) Qt_h = scale * Qs_h @ Wk_h  (batched over (b,h): M=u, N=D, K=DH) -> fp16
    sgemm64<false, true><<<dim3(D_ / 64, 1, B_ * H_), 256>>>(
        Qs, Wk, Qthi, u, D_, DH_, D_, D_, D_, H_, 1,
        (long)u * D_, DH_, 0, (long)DH_ * D_, (long)MP_ * D_, (long)u * D_,
        nullptr, 0.125f);

    // 4) S[b] = Qt[b] @ x[b]^T  (fp16 mma NT: M=768, N=4096, K=1024)
    hgemm<true><<<dim3(T_ / 128, MP_ / 128, B_), 256, HG_SMEM>>>(
        Qthi, Xhi, S, D_, T_, D_,
        (long)MP_ * D_, (long)T_ * D_, (long)MP_ * T_);

    // 5) softmax -> P fp16
    softmax_kernel<<<B_ * MQ, 256>>>(u);

    // 6) AX[b] = P[b] @ x[b]  (fp16 mma NN, x in natural layout: M=768, N=1024, K=4096)
    hgemm<false><<<dim3(D_ / 128, MP_ / 128, B_), 256, HG_SMEM>>>(
        Phi, Xhi, AX, T_, D_, D_,
        (long)MP_ * T_, (long)T_ * D_, (long)MP_ * D_);

    // 7) ctx_h = AX_h @ Wv_h^T  (batched over (b,h): M=u, N=DH, K=D; K-split x4)
    sgemm64<true, false><<<dim3(1, 1, B_ * H_ * KS), 256>>>(
        AX, Wv, CT, u, DH_, D_, D_, D_, DH_, H_, KS,
        (long)MP_ * D_, (long)u * D_, 0, (long)DH_ * D_,
        (long)H_ * u * DH_, (long)u * DH_, nullptr, 1.f);

    // 8-9) mean, assemble rows
    mean_kernel<<<dim3(H_, B_), 64>>>(u);
    yrows_kernel<<<dim3(u + 1, B_), 256>>>(u);

    // 10) O = Y @ Wo^T + bo  (M=B*(u+1), N=D, K=D; K-split x4)
    sgemm64<true, false><<<dim3(D_ / 64, (B_ * (u + 1) + 63) / 64, KS), 256>>>(
        Y, Wo, O, B_ * (u + 1), D_, D_, D_, D_, D_, 1, KS,
        0, 0, 0, 0, 0, 0, bo, 1.f);

    // 11-12) broadcast + scatter
    long total4 = (long)B_ * T_ * (D_ / 4);
    bcast_kernel<<<(unsigned)((total4 + 255) / 256), 256>>>((float4*)d_out, O, u);
    scatter_kernel<<<dim3(u, B_), 256>>>((float*)d_out, idx, u);
}

// round 12
// speedup vs baseline: 6.7988x; 1.0454x over previous
#include <cuda_runtime.h>
#include <cuda_fp16.h>
#include <cstdint>

// Problem constants
#define B_  8
#define T_  4096
#define D_  1024
#define H_  16
#define DH_ 64
#define UMAX 44
#define MP_ 768     // padded M rows per batch (>= H*u = 656), multiple of 128

// ---------------- scratch (device globals; zero-initialized) ----------------
__device__ float  g_Xs [B_*UMAX*D_];
__device__ float  g_Qs [B_*UMAX*D_];
__device__ __half g_Qthi[(long)B_*MP_*D_];     // padded rows stay zero
__device__ __half g_Xhi [(long)B_*T_*D_];
__device__ __half g_S   [(long)B_*MP_*T_];     // scores (fp16)
__device__ __half g_Phi [(long)B_*MP_*T_];     // attn probs fp16 (padded rows zero)
__device__ float  g_AX  [(long)B_*MP_*D_];
__device__ float  g_ctx [B_*H_*UMAX*DH_];
__device__ float  g_mn  [B_*H_*DH_];
__device__ float  g_Y   [B_*(UMAX+1)*D_];
__device__ float  g_O   [B_*(UMAX+1)*D_];

// ================= helpers =================
__device__ __forceinline__ uint32_t smem_u32(const void* p) {
    uint32_t a;
    asm("{ .reg .u64 t; cvta.to.shared.u64 t, %1; cvt.u32.u64 %0, t; }" : "=r"(a) : "l"(p));
    return a;
}
__device__ __forceinline__ void ldsm4(uint32_t& r0, uint32_t& r1, uint32_t& r2, uint32_t& r3,
                                      uint32_t a) {
    asm volatile("ldmatrix.sync.aligned.m8n8.x4.shared.b16 {%0,%1,%2,%3}, [%4];"
                 : "=r"(r0), "=r"(r1), "=r"(r2), "=r"(r3) : "r"(a));
}
__device__ __forceinline__ void ldsm4t(uint32_t& r0, uint32_t& r1, uint32_t& r2, uint32_t& r3,
                                       uint32_t a) {
    asm volatile("ldmatrix.sync.aligned.m8n8.x4.trans.shared.b16 {%0,%1,%2,%3}, [%4];"
                 : "=r"(r0), "=r"(r1), "=r"(r2), "=r"(r3) : "r"(a));
}
__device__ __forceinline__ void mma16816(float* d, const uint32_t* a, const uint32_t* b) {
    asm volatile("mma.sync.aligned.m16n8k16.row.col.f32.f16.f16.f32 "
                 "{%0,%1,%2,%3}, {%4,%5,%6,%7}, {%8,%9}, {%0,%1,%2,%3};"
                 : "+f"(d[0]), "+f"(d[1]), "+f"(d[2]), "+f"(d[3])
                 : "r"(a[0]), "r"(a[1]), "r"(a[2]), "r"(a[3]), "r"(b[0]), "r"(b[1]));
}
__device__ __forceinline__ void cp16(uint32_t s, const void* g) {
    asm volatile("cp.async.cg.shared.global [%0], [%1], 16;" :: "r"(s), "l"(g));
}
#define CP_COMMIT() asm volatile("cp.async.commit_group;" ::: "memory")
#define CP_WAIT(n)  asm volatile("cp.async.wait_group %0;" :: "n"(n) : "memory")

// ================= fp16 tensor-core GEMM (cp.async 3-stage, SW128) ==========
// NT: C[m,n] = sum_k A[m,k]*B[n,k]  (B row-major [N][K], ldb = K)
// NN: C[m,n] = sum_k A[m,k]*B[k,n]  (B row-major [K][N], ldb = ldbB)
// fp32 accum; C stored fp32 or fp16 (HALF_C). M,N mult of 128, K mult of 64.
#define BK 64
#define TILE_B (128 * BK * 2)      // 16384 bytes per tile
#define HG_SMEM (3 * 2 * TILE_B)   // 98304 (3-stage)

template<bool NT, bool HALF_C>
__global__ void __launch_bounds__(256, 2)
hgemm(const __half* __restrict__ A, const __half* __restrict__ B,
      void* __restrict__ Cv, int K, int N, int ldbB, long sA, long sB, long sC)
{
    extern __shared__ char dsm[];
    const uint32_t sb = smem_u32(dsm);
    const int tid = threadIdx.x, lane = tid & 31, wid = tid >> 5;
    const int bz = blockIdx.z;
    const int m0 = blockIdx.y * 128, n0 = blockIdx.x * 128;
    const int wm = (wid & 3) * 32, wn = (wid >> 2) * 64;
    const __half* Ab = A + (long)bz * sA + (long)m0 * K;
    const __half* Bb = NT ? (B + (long)bz * sB + (long)n0 * K)
                          : (B + (long)bz * sB + n0);

    float acc[2][8][4];
    #pragma unroll
    for (int i = 0; i < 2; i++)
        #pragma unroll
        for (int j = 0; j < 8; j++)
            #pragma unroll
            for (int q = 0; q < 4; q++) acc[i][j][q] = 0.f;

    const int fr = lane & 15, fc8 = lane >> 4;
    const int NCH = K / BK;

    auto issue = [&](int c) {
        const uint32_t base = sb + (uint32_t)(c % 3) * (2 * TILE_B);
        #pragma unroll
        for (int i = 0; i < 4; i++) {
            int idx = tid + i * 256;          // 0..1023
            int row = idx >> 3, cg = idx & 7;
            int phys = cg ^ (row & 7);
            cp16(base + (uint32_t)(row * 128 + phys * 16),
                 Ab + (long)row * K + c * BK + cg * 8);
        }
        if (NT) {
            #pragma unroll
            for (int i = 0; i < 4; i++) {
                int idx = tid + i * 256;
                int row = idx >> 3, cg = idx & 7;
                int phys = cg ^ (row & 7);
                cp16(base + TILE_B + (uint32_t)(row * 128 + phys * 16),
                     Bb + (long)row * K + c * BK + cg * 8);
            }
        } else {
            #pragma unroll
            for (int i = 0; i < 4; i++) {
                int idx = tid + i * 256;
                int row = idx >> 4, cg = idx & 15;
                int phys = cg ^ (row & 7);
                cp16(base + TILE_B + (uint32_t)(row * 256 + phys * 16),
                     Bb + (long)(c * BK + row) * ldbB + cg * 8);
            }
        }
    };

    issue(0); CP_COMMIT();
    issue(1); CP_COMMIT();
    for (int c = 0; c < NCH; c++) {
        CP_WAIT(1);
        __syncthreads();
        if (c + 2 < NCH) { issue(c + 2); CP_COMMIT(); }

        const uint32_t abase = sb + (uint32_t)(c % 3) * (2 * TILE_B);
        const uint32_t bbase = abase + TILE_B;
        #pragma unroll
        for (int kk = 0; kk < 4; kk++) {
            uint32_t a8[2][4], bh[8][2];
            #pragma unroll
            for (int mt = 0; mt < 2; mt++) {
                int row = wm + mt * 16 + fr;
                int cg = kk * 2 + fc8;
                int phys = cg ^ (row & 7);
                ldsm4(a8[mt][0], a8[mt][1], a8[mt][2], a8[mt][3],
                      abase + row * 128 + phys * 16);
            }
            #pragma unroll
            for (int p = 0; p < 4; p++) {
                uint32_t r0, r1, r2, r3;
                if (NT) {
                    int row = wn + p * 16 + fr;
                    int cg = kk * 2 + fc8;
                    int phys = cg ^ (row & 7);
                    ldsm4(r0, r1, r2, r3, bbase + row * 128 + phys * 16);
                } else {
                    int g = lane >> 3, j = lane & 7;
                    int krow = kk * 16 + ((g >> 1) << 3) + j;
                    int nchunk = ((wn + p * 16) >> 3) + (g & 1);
                    int phys = nchunk ^ (krow & 7);
                    ldsm4t(r0, r1, r2, r3, bbase + krow * 256 + phys * 16);
                }
                bh[2*p][0] = r0; bh[2*p+1][0] = r1; bh[2*p][1] = r2; bh[2*p+1][1] = r3;
            }
            #pragma unroll
            for (int mt = 0; mt < 2; mt++)
                #pragma unroll
                for (int nt = 0; nt < 8; nt++)
                    mma16816(acc[mt][nt], a8[mt], bh[nt]);
        }
    }

    const int qr = lane >> 2, qc = (lane & 3) * 2;
    #pragma unroll
    for (int mt = 0; mt < 2; mt++)
        #pragma unroll
        for (int nt = 0; nt < 8; nt++) {
            long r = m0 + wm + mt * 16 + qr;
            int cc = n0 + wn + nt * 8 + qc;
            if (HALF_C) {
                __half* Cb = (__half*)Cv + (long)bz * sC;
                *reinterpret_cast<__half2*>(&Cb[r * N + cc]) =
                    __floats2half2_rn(acc[mt][nt][0], acc[mt][nt][1]);
                *reinterpret_cast<__half2*>(&Cb[(r + 8) * N + cc]) =
                    __floats2half2_rn(acc[mt][nt][2], acc[mt][nt][3]);
            } else {
                float* Cb = (float*)Cv + (long)bz * sC;
                *reinterpret_cast<float2*>(&Cb[r * N + cc]) =
                    make_float2(acc[mt][nt][0], acc[mt][nt][1]);
                *reinterpret_cast<float2*>(&Cb[(r + 8) * N + cc]) =
                    make_float2(acc[mt][nt][2], acc[mt][nt][3]);
            }
        }
}

// ================= batched 64x64-tile SIMT GEMM with K-split =================
template<bool NT, bool HALF_OUT>
__global__ void __launch_bounds__(256)
sgemm64(const float* __restrict__ A, const float* __restrict__ B, void* __restrict__ Cv,
        int M, int N, int K, int lda, int ldb, int ldc, int ZH, int ZK,
        long sAb, long sAh, long sBb, long sBh, long sCb, long sCh,
        const float* __restrict__ bias, float alpha)
{
    const int zk = blockIdx.z % ZK;
    const int zt = blockIdx.z / ZK;
    const int zb = zt / ZH, zh = zt % ZH;
    A += (long)zb * sAb + (long)zh * sAh;
    B += (long)zb * sBb + (long)zh * sBh;
    const long coff = (long)zb * sCb + (long)zh * sCh;

    __shared__ float As[16][68];
    __shared__ float Bs[16][68];

    const int m0 = blockIdx.y * 64, n0 = blockIdx.x * 64;
    const int tid = threadIdx.x;
    const int lr = tid >> 2;
    const int lk = (tid & 3) * 4;
    const int bk = tid >> 4;
    const int bn = (tid & 15) * 4;
    const int tm = (tid >> 4) * 4, tn = (tid & 15) * 4;

    float acc[4][4];
    #pragma unroll
    for (int i = 0; i < 4; i++)
        #pragma unroll
        for (int j = 0; j < 4; j++) acc[i][j] = 0.f;

    const int Kc = K / ZK;
    const int kbeg = zk * Kc, kend = kbeg + Kc;

    for (int k0 = kbeg; k0 < kend; k0 += 16) {
        {
            float4 v = make_float4(0.f, 0.f, 0.f, 0.f);
            int gm = m0 + lr;
            if (gm < M) v = *reinterpret_cast<const float4*>(A + (long)gm * lda + k0 + lk);
            As[lk + 0][lr] = v.x; As[lk + 1][lr] = v.y;
            As[lk + 2][lr] = v.z; As[lk + 3][lr] = v.w;
        }
        if (NT) {
            float4 v = *reinterpret_cast<const float4*>(B + (long)(n0 + lr) * ldb + k0 + lk);
            Bs[lk + 0][lr] = v.x; Bs[lk + 1][lr] = v.y;
            Bs[lk + 2][lr] = v.z; Bs[lk + 3][lr] = v.w;
        } else {
            float4 v = *reinterpret_cast<const float4*>(B + (long)(k0 + bk) * ldb + n0 + bn);
            *reinterpret_cast<float4*>(&Bs[bk][bn]) = v;
        }
        __syncthreads();

        #pragma unroll
        for (int kk = 0; kk < 16; kk++) {
            float ar[4], br[4];
            *reinterpret_cast<float4*>(ar) = *reinterpret_cast<const float4*>(&As[kk][tm]);
            *reinterpret_cast<float4*>(br) = *reinterpret_cast<const float4*>(&Bs[kk][tn]);
            #pragma unroll
            for (int i = 0; i < 4; i++)
                #pragma unroll
                for (int j = 0; j < 4; j++) acc[i][j] += ar[i] * br[j];
        }
        __syncthreads();
    }

    #pragma unroll
    for (int i = 0; i < 4; i++) {
        int gm = m0 + tm + i;
        if (gm >= M) break;
        #pragma unroll
        for (int j = 0; j < 4; j++) {
            int gn = n0 + tn + j;
            float v = acc[i][j] * alpha;
            if (bias && zk == 0) v += bias[gn];
            if (HALF_OUT) {
                ((__half*)Cv)[coff + (long)gm * ldc + gn] = __float2half_rn(v);
            } else if (ZK > 1) {
                atomicAdd(&((float*)Cv)[coff + (long)gm * ldc + gn], v);
            } else {
                ((float*)Cv)[coff + (long)gm * ldc + gn] = v;
            }
        }
    }
}

// ---------------- small kernels ----------------
__global__ void zero3_kernel(float4* __restrict__ a, long na,
                             float4* __restrict__ b, long nb,
                             float4* __restrict__ c, long nc)
{
    long i = (long)blockIdx.x * blockDim.x + threadIdx.x;
    float4 z = make_float4(0.f, 0.f, 0.f, 0.f);
    if (i < na) a[i] = z;
    if (i < nb) b[i] = z;
    if (i < nc) c[i] = z;
}

__global__ void conv_x_kernel(const float* __restrict__ x)
{
    long i = ((long)blockIdx.x * blockDim.x + threadIdx.x);
    long n4 = (long)B_ * T_ * D_ / 4;
    if (i >= n4) return;
    float4 v = reinterpret_cast<const float4*>(x)[i];
    __half h[4];
    h[0] = __float2half_rn(v.x); h[1] = __float2half_rn(v.y);
    h[2] = __float2half_rn(v.z); h[3] = __float2half_rn(v.w);
    *reinterpret_cast<uint2*>(&g_Xhi[i * 4]) = *reinterpret_cast<uint2*>(h);
}

__global__ void gather_kernel(const float* __restrict__ x, const int* __restrict__ idx, int u)
{
    int j = blockIdx.x, b = blockIdx.y;
    int t = idx[j];
    const float4* src = reinterpret_cast<const float4*>(x + ((long)b * T_ + t) * D_);
    float4* dst = reinterpret_cast<float4*>(g_Xs + ((long)b * u + j) * D_);
    dst[threadIdx.x] = src[threadIdx.x];
}

// softmax over T (fp16 scores in, fp16 probs out), half2 vectorized
__global__ void softmax_kernel(int u)
{
    int MQ = H_ * u;
    int r = blockIdx.x % MQ, b = blockIdx.x / MQ;
    long row = (long)b * MP_ + r;
    const __half2* s2 = reinterpret_cast<const __half2*>(g_S + row * T_);
    __half2* p2 = reinterpret_cast<__half2*>(g_Phi + row * T_);
    int tid = threadIdx.x;   // 256
    __shared__ float red[256];
    const int NT2 = T_ / 2;  // 2048

    float mx = -1e30f;
    for (int t = tid; t < NT2; t += 256) {
        float2 v = __half22float2(s2[t]);
        mx = fmaxf(mx, fmaxf(v.x, v.y));
    }
    red[tid] = mx; __syncthreads();
    for (int o = 128; o > 0; o >>= 1) { if (tid < o) red[tid] = fmaxf(red[tid], red[tid + o]); __syncthreads(); }
    mx = red[0]; __syncthreads();

    float sum = 0.f;
    for (int t = tid; t < NT2; t += 256) {
        float2 v = __half22float2(s2[t]);
        sum += __expf(v.x - mx) + __expf(v.y - mx);
    }
    red[tid] = sum; __syncthreads();
    for (int o = 128; o > 0; o >>= 1) { if (tid < o) red[tid] += red[tid + o]; __syncthreads(); }
    float inv = 1.f / red[0];
    for (int t = tid; t < NT2; t += 256) {
        float2 v = __half22float2(s2[t]);
        p2[t] = __floats2half2_rn(__expf(v.x - mx) * inv, __expf(v.y - mx) * inv);
    }
}

__global__ void mean_kernel(int u)
{
    int h = blockIdx.x, b = blockIdx.y;
    int e = threadIdx.x;   // 64
    float s = 0.f;
    const float* base = g_ctx + (long)(b * H_ + h) * u * DH_ + e;
    for (int j = 0; j < u; j++) s += base[(long)j * DH_];
    g_mn[(b * H_ + h) * DH_ + e] = s / (float)u;
}

__global__ void yrows_kernel(int u)
{
    int r = blockIdx.x, b = blockIdx.y;
    int tid = threadIdx.x;   // 256
    float* out = g_Y + ((long)b * (u + 1) + r) * D_;
    #pragma unroll
    for (int q = 0; q < 4; q++) {
        int d = tid * 4 + q;
        int h = d >> 6, e = d & 63;
        float v = (r == 0) ? g_mn[(b * H_ + h) * DH_ + e]
                           : g_ctx[((long)(b * H_ + h) * u + (r - 1)) * DH_ + e];
        out[d] = v;
    }
}

__global__ void bcast_kernel(float4* __restrict__ out, const float* __restrict__ O, int u)
{
    long i = (long)blockIdx.x * blockDim.x + threadIdx.x;
    long total = (long)B_ * T_ * (D_ / 4);
    if (i >= total) return;
    int d4 = (int)(i & 255);
    long bt = i >> 8;
    int b = (int)(bt >> 12);
    out[i] = reinterpret_cast<const float4*>(O + (long)b * (u + 1) * D_)[d4];
}

__global__ void scatter_kernel(float* __restrict__ out, const int* __restrict__ idx, int u)
{
    int j = blockIdx.x, b = blockIdx.y;
    int t = idx[j];
    const float4* src = reinterpret_cast<const float4*>(g_O + ((long)b * (u + 1) + 1 + j) * D_);
    float4* dst = reinterpret_cast<float4*>(out + ((long)b * T_ + t) * D_);
    dst[threadIdx.x] = src[threadIdx.x];
}

// ---------------- host launch ----------------
template<typename Tp>
static Tp* symaddr_t(const void* sym)
{
    void* p = nullptr;
    cudaGetSymbolAddress(&p, sym);
    return (Tp*)p;
}

extern "C" void kernel_launch(void* const* d_in, const int* in_sizes, int n_in,
                              void* d_out, int out_size)
{
    const float* x  = (const float*)d_in[0];
    const float* Wq = (const float*)d_in[1];
    const float* Wk = (const float*)d_in[2];
    const float* Wv = (const float*)d_in[3];
    const float* Wo = (const float*)d_in[4];
    const float* bo = (const float*)d_in[5];
    const int*  idx = (const int*)d_in[6];
    const int u = in_sizes[6];            // 41

    cudaFuncSetAttribute((const void*)hgemm<true, true>,
                         cudaFuncAttributeMaxDynamicSharedMemorySize, HG_SMEM);
    cudaFuncSetAttribute((const void*)hgemm<false, false>,
                         cudaFuncAttributeMaxDynamicSharedMemorySize, HG_SMEM);

    float* Xs = symaddr_t<float>(g_Xs);
    float* Qs = symaddr_t<float>(g_Qs);
    float* AX = symaddr_t<float>(g_AX);
    float* Y  = symaddr_t<float>(g_Y);
    float* O  = symaddr_t<float>(g_O);
    float* CT = symaddr_t<float>(g_ctx);
    __half* Qthi = symaddr_t<__half>(g_Qthi);
    __half* Xhi  = symaddr_t<__half>(g_Xhi);
    __half* S    = symaddr_t<__half>(g_S);
    __half* Phi  = symaddr_t<__half>(g_Phi);

    const int MQ = H_ * u;                // 656
    const int KS = 4;                     // K-split factor for starved gemms

    // 0) zero atomic-accumulation targets (one launch)
    {
        long na = B_*UMAX*D_/4, nb = B_*H_*UMAX*DH_/4, nc = (long)B_*(UMAX+1)*D_/4;
        long nm = na > nb ? na : nb; if (nc > nm) nm = nc;
        zero3_kernel<<<(unsigned)((nm + 255)/256), 256>>>(
            (float4*)Qs, na, (float4*)CT, nb, (float4*)O, nc);
    }

    // 1) gather query rows; fp16 conversion of x
    gather_kernel<<<dim3(u, B_), 256>>>(x, idx, u);
    {
        long n4 = (long)B_ * T_ * D_ / 4;
        conv_x_kernel<<<(unsigned)((n4 + 255) / 256), 256>>>(x);
    }

    // 2) Qs = Xs @ Wq^T  (M=B*u, N=D, K=D; K-split x4)
    sgemm64<true, false><<<dim3(D_ / 64, (B_ * u + 63) / 64, KS), 256>>>(
        Xs, Wq, Qs, B_ * u, D_, D_, D_, D_, D_, 1, KS,
        0, 0, 0, 0, 0, 0, nullptr, 1.f);

    // 3) Qt_h = scale * Qs_h @ Wk_h  (batched over (b,h): M=u, N=D, K=DH) -> fp16
    sgemm64<false, true><<<dim3(D_ / 64, 1, B_ * H_), 256>>>(
        Qs, Wk, Qthi, u, D_, DH_, D_, D_, D_, H_, 1,
        (long)u * D_, DH_, 0, (long)DH_ * D_, (long)MP_ * D_, (long)u * D_,
        nullptr, 0.125f);

    // 4) S[b] = Qt[b] @ x[b]^T  (fp16 mma NT, fp16 out: M=768, N=4096, K=1024)
    hgemm<true, true><<<dim3(T_ / 128, MP_ / 128, B_), 256, HG_SMEM>>>(
        Qthi, Xhi, S, D_, T_, D_,
        (long)MP_ * D_, (long)T_ * D_, (long)MP_ * T_);

    // 5) softmax (fp16 in) -> P fp16
    softmax_kernel<<<B_ * MQ, 256>>>(u);

    // 6) AX[b] = P[b] @ x[b]  (fp16 mma NN, fp32 out: M=768, N=1024, K=4096)
    hgemm<false, false><<<dim3(D_ / 128, MP_ / 128, B_), 256, HG_SMEM>>>(
        Phi, Xhi, AX, T_, D_, D_,
        (long)MP_ * T_, (long)T_ * D_, (long)MP_ * D_);

    // 7) ctx_h = AX_h @ Wv_h^T  (batched over (b,h): M=u, N=DH, K=D; K-split x4)
    sgemm64<true, false><<<dim3(1, 1, B_ * H_ * KS), 256>>>(
        AX, Wv, CT, u, DH_, D_, D_, D_, DH_, H_, KS,
        (long)MP_ * D_, (long)u * D_, 0, (long)DH_ * D_,
        (long)H_ * u * DH_, (long)u * DH_, nullptr, 1.f);

    // 8-9) mean, assemble rows
    mean_kernel<<<dim3(H_, B_), 64>>>(u);
    yrows_kernel<<<dim3(u + 1, B_), 256>>>(u);

    // 10) O = Y @ Wo^T + bo  (M=B*(u+1), N=D, K=D; K-split x4)
    sgemm64<true, false><<<dim3(D_ / 64, (B_ * (u + 1) + 63) / 64, KS), 256>>>(
        Y, Wo, O, B_ * (u + 1), D_, D_, D_, D_, D_, 1, KS,
        0, 0, 0, 0, 0, 0, bo, 1.f);

    // 11-12) broadcast + scatter
    long total4 = (long)B_ * T_ * (D_ / 4);
    bcast_kernel<<<(unsigned)((total4 + 255) / 256), 256>>>((float4*)d_out, O, u);
    scatter_kernel<<<dim3(u, B_), 256>>>((float*)d_out, idx, u);
}

// round 14
// speedup vs baseline: 7.1192x; 1.0471x over previous
#include <cuda_runtime.h>
#include <cuda_fp16.h>
#include <cstdint>

// Problem constants
#define B_  8
#define T_  4096
#define D_  1024
#define H_  16
#define DH_ 64
#define UMAX 44
#define MP_ 768     // padded M rows per batch (>= H*u = 656), multiple of 128

// ---------------- scratch (device globals; zero-initialized) ----------------
__device__ float  g_Xs [B_*UMAX*D_];
__device__ float  g_Qs [B_*UMAX*D_];
__device__ __half g_Qthi[(long)B_*MP_*D_];     // padded rows stay zero
__device__ __half g_Xhi [(long)B_*T_*D_];
__device__ __half g_S   [(long)B_*MP_*T_];     // scores (fp16)
__device__ __half g_Phi [(long)B_*MP_*T_];     // attn probs fp16 (padded rows zero)
__device__ float  g_AX  [(long)B_*MP_*D_];
__device__ float  g_ctx [B_*H_*UMAX*DH_];
__device__ float  g_mn  [B_*H_*DH_];
__device__ float  g_Y   [B_*(UMAX+1)*D_];
__device__ float  g_O   [B_*(UMAX+1)*D_];

// ================= helpers =================
__device__ __forceinline__ uint32_t smem_u32(const void* p) {
    uint32_t a;
    asm("{ .reg .u64 t; cvta.to.shared.u64 t, %1; cvt.u32.u64 %0, t; }" : "=r"(a) : "l"(p));
    return a;
}
__device__ __forceinline__ void ldsm4(uint32_t& r0, uint32_t& r1, uint32_t& r2, uint32_t& r3,
                                      uint32_t a) {
    asm volatile("ldmatrix.sync.aligned.m8n8.x4.shared.b16 {%0,%1,%2,%3}, [%4];"
                 : "=r"(r0), "=r"(r1), "=r"(r2), "=r"(r3) : "r"(a));
}
__device__ __forceinline__ void ldsm4t(uint32_t& r0, uint32_t& r1, uint32_t& r2, uint32_t& r3,
                                       uint32_t a) {
    asm volatile("ldmatrix.sync.aligned.m8n8.x4.trans.shared.b16 {%0,%1,%2,%3}, [%4];"
                 : "=r"(r0), "=r"(r1), "=r"(r2), "=r"(r3) : "r"(a));
}
__device__ __forceinline__ void mma16816(float* d, const uint32_t* a, const uint32_t* b) {
    asm volatile("mma.sync.aligned.m16n8k16.row.col.f32.f16.f16.f32 "
                 "{%0,%1,%2,%3}, {%4,%5,%6,%7}, {%8,%9}, {%0,%1,%2,%3};"
                 : "+f"(d[0]), "+f"(d[1]), "+f"(d[2]), "+f"(d[3])
                 : "r"(a[0]), "r"(a[1]), "r"(a[2]), "r"(a[3]), "r"(b[0]), "r"(b[1]));
}
__device__ __forceinline__ void cp16(uint32_t s, const void* g) {
    asm volatile("cp.async.cg.shared.global [%0], [%1], 16;" :: "r"(s), "l"(g));
}
#define CP_COMMIT() asm volatile("cp.async.commit_group;" ::: "memory")
#define CP_WAIT(n)  asm volatile("cp.async.wait_group %0;" :: "n"(n) : "memory")

// ================= fp16 tensor-core GEMM (cp.async 3-stage, SW128) ==========
// NT: C[m,n] = sum_k A[m,k]*B[n,k]  (B row-major [N][K], ldb = K)
// NN: C[m,n] = sum_k A[m,k]*B[k,n]  (B row-major [K][N], ldb = ldbB)
// fp32 accum; C stored fp32 or fp16 (HALF_C). M,N mult of 128, K mult of 64.
#define BK 64
#define TILE_B (128 * BK * 2)      // 16384 bytes per tile
#define HG_SMEM (3 * 2 * TILE_B)   // 98304 (3-stage)

template<bool NT, bool HALF_C>
__global__ void __launch_bounds__(256, 2)
hgemm(const __half* __restrict__ A, const __half* __restrict__ B,
      void* __restrict__ Cv, int K, int N, int ldbB, long sA, long sB, long sC)
{
    extern __shared__ char dsm[];
    const uint32_t sb = smem_u32(dsm);
    const int tid = threadIdx.x, lane = tid & 31, wid = tid >> 5;
    const int bz = blockIdx.z;
    const int m0 = blockIdx.y * 128, n0 = blockIdx.x * 128;
    const int wm = (wid & 3) * 32, wn = (wid >> 2) * 64;
    const __half* Ab = A + (long)bz * sA + (long)m0 * K;
    const __half* Bb = NT ? (B + (long)bz * sB + (long)n0 * K)
                          : (B + (long)bz * sB + n0);

    float acc[2][8][4];
    #pragma unroll
    for (int i = 0; i < 2; i++)
        #pragma unroll
        for (int j = 0; j < 8; j++)
            #pragma unroll
            for (int q = 0; q < 4; q++) acc[i][j][q] = 0.f;

    const int fr = lane & 15, fc8 = lane >> 4;
    const int NCH = K / BK;

    auto issue = [&](int c) {
        const uint32_t base = sb + (uint32_t)(c % 3) * (2 * TILE_B);
        #pragma unroll
        for (int i = 0; i < 4; i++) {
            int idx = tid + i * 256;          // 0..1023
            int row = idx >> 3, cg = idx & 7;
            int phys = cg ^ (row & 7);
            cp16(base + (uint32_t)(row * 128 + phys * 16),
                 Ab + (long)row * K + c * BK + cg * 8);
        }
        if (NT) {
            #pragma unroll
            for (int i = 0; i < 4; i++) {
                int idx = tid + i * 256;
                int row = idx >> 3, cg = idx & 7;
                int phys = cg ^ (row & 7);
                cp16(base + TILE_B + (uint32_t)(row * 128 + phys * 16),
                     Bb + (long)row * K + c * BK + cg * 8);
            }
        } else {
            #pragma unroll
            for (int i = 0; i < 4; i++) {
                int idx = tid + i * 256;
                int row = idx >> 4, cg = idx & 15;
                int phys = cg ^ (row & 7);
                cp16(base + TILE_B + (uint32_t)(row * 256 + phys * 16),
                     Bb + (long)(c * BK + row) * ldbB + cg * 8);
            }
        }
    };

    issue(0); CP_COMMIT();
    issue(1); CP_COMMIT();
    for (int c = 0; c < NCH; c++) {
        CP_WAIT(1);
        __syncthreads();
        if (c + 2 < NCH) { issue(c + 2); CP_COMMIT(); }

        const uint32_t abase = sb + (uint32_t)(c % 3) * (2 * TILE_B);
        const uint32_t bbase = abase + TILE_B;
        #pragma unroll
        for (int kk = 0; kk < 4; kk++) {
            uint32_t a8[2][4], bh[8][2];
            #pragma unroll
            for (int mt = 0; mt < 2; mt++) {
                int row = wm + mt * 16 + fr;
                int cg = kk * 2 + fc8;
                int phys = cg ^ (row & 7);
                ldsm4(a8[mt][0], a8[mt][1], a8[mt][2], a8[mt][3],
                      abase + row * 128 + phys * 16);
            }
            #pragma unroll
            for (int p = 0; p < 4; p++) {
                uint32_t r0, r1, r2, r3;
                if (NT) {
                    int row = wn + p * 16 + fr;
                    int cg = kk * 2 + fc8;
                    int phys = cg ^ (row & 7);
                    ldsm4(r0, r1, r2, r3, bbase + row * 128 + phys * 16);
                } else {
                    int g = lane >> 3, j = lane & 7;
                    int krow = kk * 16 + ((g >> 1) << 3) + j;
                    int nchunk = ((wn + p * 16) >> 3) + (g & 1);
                    int phys = nchunk ^ (krow & 7);
                    ldsm4t(r0, r1, r2, r3, bbase + krow * 256 + phys * 16);
                }
                bh[2*p][0] = r0; bh[2*p+1][0] = r1; bh[2*p][1] = r2; bh[2*p+1][1] = r3;
            }
            #pragma unroll
            for (int mt = 0; mt < 2; mt++)
                #pragma unroll
                for (int nt = 0; nt < 8; nt++)
                    mma16816(acc[mt][nt], a8[mt], bh[nt]);
        }
    }

    const int qr = lane >> 2, qc = (lane & 3) * 2;
    #pragma unroll
    for (int mt = 0; mt < 2; mt++)
        #pragma unroll
        for (int nt = 0; nt < 8; nt++) {
            long r = m0 + wm + mt * 16 + qr;
            int cc = n0 + wn + nt * 8 + qc;
            if (HALF_C) {
                __half* Cb = (__half*)Cv + (long)bz * sC;
                *reinterpret_cast<__half2*>(&Cb[r * N + cc]) =
                    __floats2half2_rn(acc[mt][nt][0], acc[mt][nt][1]);
                *reinterpret_cast<__half2*>(&Cb[(r + 8) * N + cc]) =
                    __floats2half2_rn(acc[mt][nt][2], acc[mt][nt][3]);
            } else {
                float* Cb = (float*)Cv + (long)bz * sC;
                *reinterpret_cast<float2*>(&Cb[r * N + cc]) =
                    make_float2(acc[mt][nt][0], acc[mt][nt][1]);
                *reinterpret_cast<float2*>(&Cb[(r + 8) * N + cc]) =
                    make_float2(acc[mt][nt][2], acc[mt][nt][3]);
            }
        }
}

// ================= batched 64x64-tile SIMT GEMM with K-split =================
template<bool NT, bool HALF_OUT>
__global__ void __launch_bounds__(256)
sgemm64(const float* __restrict__ A, const float* __restrict__ B, void* __restrict__ Cv,
        int M, int N, int K, int lda, int ldb, int ldc, int ZH, int ZK,
        long sAb, long sAh, long sBb, long sBh, long sCb, long sCh,
        const float* __restrict__ bias, float alpha)
{
    const int zk = blockIdx.z % ZK;
    const int zt = blockIdx.z / ZK;
    const int zb = zt / ZH, zh = zt % ZH;
    A += (long)zb * sAb + (long)zh * sAh;
    B += (long)zb * sBb + (long)zh * sBh;
    const long coff = (long)zb * sCb + (long)zh * sCh;

    __shared__ float As[16][68];
    __shared__ float Bs[16][68];

    const int m0 = blockIdx.y * 64, n0 = blockIdx.x * 64;
    const int tid = threadIdx.x;
    const int lr = tid >> 2;
    const int lk = (tid & 3) * 4;
    const int bk = tid >> 4;
    const int bn = (tid & 15) * 4;
    const int tm = (tid >> 4) * 4, tn = (tid & 15) * 4;

    float acc[4][4];
    #pragma unroll
    for (int i = 0; i < 4; i++)
        #pragma unroll
        for (int j = 0; j < 4; j++) acc[i][j] = 0.f;

    const int Kc = K / ZK;
    const int kbeg = zk * Kc, kend = kbeg + Kc;

    for (int k0 = kbeg; k0 < kend; k0 += 16) {
        {
            float4 v = make_float4(0.f, 0.f, 0.f, 0.f);
            int gm = m0 + lr;
            if (gm < M) v = *reinterpret_cast<const float4*>(A + (long)gm * lda + k0 + lk);
            As[lk + 0][lr] = v.x; As[lk + 1][lr] = v.y;
            As[lk + 2][lr] = v.z; As[lk + 3][lr] = v.w;
        }
        if (NT) {
            float4 v = *reinterpret_cast<const float4*>(B + (long)(n0 + lr) * ldb + k0 + lk);
            Bs[lk + 0][lr] = v.x; Bs[lk + 1][lr] = v.y;
            Bs[lk + 2][lr] = v.z; Bs[lk + 3][lr] = v.w;
        } else {
            float4 v = *reinterpret_cast<const float4*>(B + (long)(k0 + bk) * ldb + n0 + bn);
            *reinterpret_cast<float4*>(&Bs[bk][bn]) = v;
        }
        __syncthreads();

        #pragma unroll
        for (int kk = 0; kk < 16; kk++) {
            float ar[4], br[4];
            *reinterpret_cast<float4*>(ar) = *reinterpret_cast<const float4*>(&As[kk][tm]);
            *reinterpret_cast<float4*>(br) = *reinterpret_cast<const float4*>(&Bs[kk][tn]);
            #pragma unroll
            for (int i = 0; i < 4; i++)
                #pragma unroll
                for (int j = 0; j < 4; j++) acc[i][j] += ar[i] * br[j];
        }
        __syncthreads();
    }

    #pragma unroll
    for (int i = 0; i < 4; i++) {
        int gm = m0 + tm + i;
        if (gm >= M) break;
        #pragma unroll
        for (int j = 0; j < 4; j++) {
            int gn = n0 + tn + j;
            float v = acc[i][j] * alpha;
            if (bias && zk == 0) v += bias[gn];
            if (HALF_OUT) {
                ((__half*)Cv)[coff + (long)gm * ldc + gn] = __float2half_rn(v);
            } else if (ZK > 1) {
                atomicAdd(&((float*)Cv)[coff + (long)gm * ldc + gn], v);
            } else {
                ((float*)Cv)[coff + (long)gm * ldc + gn] = v;
            }
        }
    }
}

// ---------------- small kernels ----------------
__global__ void zero3_kernel(float4* __restrict__ a, long na,
                             float4* __restrict__ b, long nb,
                             float4* __restrict__ c, long nc)
{
    long i = (long)blockIdx.x * blockDim.x + threadIdx.x;
    float4 z = make_float4(0.f, 0.f, 0.f, 0.f);
    if (i < na) a[i] = z;
    if (i < nb) b[i] = z;
    if (i < nc) c[i] = z;
}

__global__ void conv_x_kernel(const float* __restrict__ x)
{
    long i = ((long)blockIdx.x * blockDim.x + threadIdx.x);
    long n4 = (long)B_ * T_ * D_ / 4;
    if (i >= n4) return;
    float4 v = reinterpret_cast<const float4*>(x)[i];
    __half h[4];
    h[0] = __float2half_rn(v.x); h[1] = __float2half_rn(v.y);
    h[2] = __float2half_rn(v.z); h[3] = __float2half_rn(v.w);
    *reinterpret_cast<uint2*>(&g_Xhi[i * 4]) = *reinterpret_cast<uint2*>(h);
}

__global__ void gather_kernel(const float* __restrict__ x, const int* __restrict__ idx, int u)
{
    int j = blockIdx.x, b = blockIdx.y;
    int t = idx[j];
    const float4* src = reinterpret_cast<const float4*>(x + ((long)b * T_ + t) * D_);
    float4* dst = reinterpret_cast<float4*>(g_Xs + ((long)b * u + j) * D_);
    dst[threadIdx.x] = src[threadIdx.x];
}

// softmax over T (fp16 in/out), half2 vectorized, exp cached in registers
__global__ void softmax_kernel(int u)
{
    int MQ = H_ * u;
    int r = blockIdx.x % MQ, b = blockIdx.x / MQ;
    long row = (long)b * MP_ + r;
    const __half2* s2 = reinterpret_cast<const __half2*>(g_S + row * T_);
    __half2* p2 = reinterpret_cast<__half2*>(g_Phi + row * T_);
    int tid = threadIdx.x;   // 256
    __shared__ float red[256];
    const int NT2 = T_ / 2;          // 2048
    const int PER = NT2 / 256;       // 8 half2 per thread

    float2 v[PER];
    float mx = -1e30f;
    #pragma unroll
    for (int q = 0; q < PER; q++) {
        v[q] = __half22float2(s2[tid + q * 256]);
        mx = fmaxf(mx, fmaxf(v[q].x, v[q].y));
    }
    red[tid] = mx; __syncthreads();
    for (int o = 128; o > 0; o >>= 1) { if (tid < o) red[tid] = fmaxf(red[tid], red[tid + o]); __syncthreads(); }
    mx = red[0]; __syncthreads();

    float sum = 0.f;
    #pragma unroll
    for (int q = 0; q < PER; q++) {
        v[q].x = __expf(v[q].x - mx);
        v[q].y = __expf(v[q].y - mx);
        sum += v[q].x + v[q].y;
    }
    red[tid] = sum; __syncthreads();
    for (int o = 128; o > 0; o >>= 1) { if (tid < o) red[tid] += red[tid + o]; __syncthreads(); }
    float inv = 1.f / red[0];
    #pragma unroll
    for (int q = 0; q < PER; q++)
        p2[tid + q * 256] = __floats2half2_rn(v[q].x * inv, v[q].y * inv);
}

__global__ void mean_kernel(int u)
{
    int h = blockIdx.x, b = blockIdx.y;
    int e = threadIdx.x;   // 64
    float s = 0.f;
    const float* base = g_ctx + (long)(b * H_ + h) * u * DH_ + e;
    for (int j = 0; j < u; j++) s += base[(long)j * DH_];
    g_mn[(b * H_ + h) * DH_ + e] = s / (float)u;
}

__global__ void yrows_kernel(int u)
{
    int r = blockIdx.x, b = blockIdx.y;
    int tid = threadIdx.x;   // 256
    float* out = g_Y + ((long)b * (u + 1) + r) * D_;
    #pragma unroll
    for (int q = 0; q < 4; q++) {
        int d = tid * 4 + q;
        int h = d >> 6, e = d & 63;
        float v = (r == 0) ? g_mn[(b * H_ + h) * DH_ + e]
                           : g_ctx[((long)(b * H_ + h) * u + (r - 1)) * DH_ + e];
        out[d] = v;
    }
}

__global__ void bcast_kernel(float4* __restrict__ out, const float* __restrict__ O, int u)
{
    long i = (long)blockIdx.x * blockDim.x + threadIdx.x;
    long total = (long)B_ * T_ * (D_ / 4);
    if (i >= total) return;
    int d4 = (int)(i & 255);
    long bt = i >> 8;
    int b = (int)(bt >> 12);
    out[i] = reinterpret_cast<const float4*>(O + (long)b * (u + 1) * D_)[d4];
}

__global__ void scatter_kernel(float* __restrict__ out, const int* __restrict__ idx, int u)
{
    int j = blockIdx.x, b = blockIdx.y;
    int t = idx[j];
    const float4* src = reinterpret_cast<const float4*>(g_O + ((long)b * (u + 1) + 1 + j) * D_);
    float4* dst = reinterpret_cast<float4*>(out + ((long)b * T_ + t) * D_);
    dst[threadIdx.x] = src[threadIdx.x];
}

// ---------------- host launch ----------------
template<typename Tp>
static Tp* symaddr_t(const void* sym)
{
    void* p = nullptr;
    cudaGetSymbolAddress(&p, sym);
    return (Tp*)p;
}

extern "C" void kernel_launch(void* const* d_in, const int* in_sizes, int n_in,
                              void* d_out, int out_size)
{
    const float* x  = (const float*)d_in[0];
    const float* Wq = (const float*)d_in[1];
    const float* Wk = (const float*)d_in[2];
    const float* Wv = (const float*)d_in[3];
    const float* Wo = (const float*)d_in[4];
    const float* bo = (const float*)d_in[5];
    const int*  idx = (const int*)d_in[6];
    const int u = in_sizes[6];            // 41

    cudaFuncSetAttribute((const void*)hgemm<true, true>,
                         cudaFuncAttributeMaxDynamicSharedMemorySize, HG_SMEM);
    cudaFuncSetAttribute((const void*)hgemm<false, false>,
                         cudaFuncAttributeMaxDynamicSharedMemorySize, HG_SMEM);

    float* Xs = symaddr_t<float>(g_Xs);
    float* Qs = symaddr_t<float>(g_Qs);
    float* AX = symaddr_t<float>(g_AX);
    float* Y  = symaddr_t<float>(g_Y);
    float* O  = symaddr_t<float>(g_O);
    float* CT = symaddr_t<float>(g_ctx);
    __half* Qthi = symaddr_t<__half>(g_Qthi);
    __half* Xhi  = symaddr_t<__half>(g_Xhi);
    __half* S    = symaddr_t<__half>(g_S);
    __half* Phi  = symaddr_t<__half>(g_Phi);

    const int MQ = H_ * u;                // 656
    const int KS = 8;                     // K-split factor for starved gemms

    // 0) zero atomic-accumulation targets (one launch)
    {
        long na = B_*UMAX*D_/4, nb = B_*H_*UMAX*DH_/4, nc = (long)B_*(UMAX+1)*D_/4;
        long nm = na > nb ? na : nb; if (nc > nm) nm = nc;
        zero3_kernel<<<(unsigned)((nm + 255)/256), 256>>>(
            (float4*)Qs, na, (float4*)CT, nb, (float4*)O, nc);
    }

    // 1) gather query rows; fp16 conversion of x
    gather_kernel<<<dim3(u, B_), 256>>>(x, idx, u);
    {
        long n4 = (long)B_ * T_ * D_ / 4;
        conv_x_kernel<<<(unsigned)((n4 + 255) / 256), 256>>>(x);
    }

    // 2) Qs = Xs @ Wq^T  (M=B*u, N=D, K=D; K-split x8)
    sgemm64<true, false><<<dim3(D_ / 64, (B_ * u + 63) / 64, KS), 256>>>(
        Xs, Wq, Qs, B_ * u, D_, D_, D_, D_, D_, 1, KS,
        0, 0, 0, 0, 0, 0, nullptr, 1.f);

    // 3) Qt_h = scale * Qs_h @ Wk_h  (batched over (b,h): M=u, N=D, K=DH) -> fp16
    sgemm64<false, true><<<dim3(D_ / 64, 1, B_ * H_), 256>>>(
        Qs, Wk, Qthi, u, D_, DH_, D_, D_, D_, H_, 1,
        (long)u * D_, DH_, 0, (long)DH_ * D_, (long)MP_ * D_, (long)u * D_,
        nullptr, 0.125f);

    // 4) S[b] = Qt[b] @ x[b]^T  (fp16 mma NT, fp16 out: M=768, N=4096, K=1024)
    hgemm<true, true><<<dim3(T_ / 128, MP_ / 128, B_), 256, HG_SMEM>>>(
        Qthi, Xhi, S, D_, T_, D_,
        (long)MP_ * D_, (long)T_ * D_, (long)MP_ * T_);

    // 5) softmax (fp16 in) -> P fp16
    softmax_kernel<<<B_ * MQ, 256>>>(u);

    // 6) AX[b] = P[b] @ x[b]  (fp16 mma NN, fp32 out: M=768, N=1024, K=4096)
    hgemm<false, false><<<dim3(D_ / 128, MP_ / 128, B_), 256, HG_SMEM>>>(
        Phi, Xhi, AX, T_, D_, D_,
        (long)MP_ * T_, (long)T_ * D_, (long)MP_ * D_);

    // 7) ctx_h = AX_h @ Wv_h^T  (batched over (b,h): M=u, N=DH, K=D; K-split x8)
    sgemm64<true, false><<<dim3(1, 1, B_ * H_ * KS), 256>>>(
        AX, Wv, CT, u, DH_, D_, D_, D_, DH_, H_, KS,
        (long)MP_ * D_, (long)u * D_, 0, (long)DH_ * D_,
        (long)H_ * u * DH_, (long)u * DH_, nullptr, 1.f);

    // 8-9) mean, assemble rows
    mean_kernel<<<dim3(H_, B_), 64>>>(u);
    yrows_kernel<<<dim3(u + 1, B_), 256>>>(u);

    // 10) O = Y @ Wo^T + bo  (M=B*(u+1), N=D, K=D; K-split x8)
    sgemm64<true, false><<<dim3(D_ / 64, (B_ * (u + 1) + 63) / 64, KS), 256>>>(
        Y, Wo, O, B_ * (u + 1), D_, D_, D_, D_, D_, 1, KS,
        0, 0, 0, 0, 0, 0, bo, 1.f);

    // 11-12) broadcast + scatter
    long total4 = (long)B_ * T_ * (D_ / 4);
    bcast_kernel<<<(unsigned)((total4 + 255) / 256), 256>>>((float4*)d_out, O, u);
    scatter_kernel<<<dim3(u, B_), 256>>>((float*)d_out, idx, u);
}

// round 16
// speedup vs baseline: 7.8396x; 1.1012x over previous
#include <cuda_runtime.h>
#include <cuda_fp16.h>
#include <cstdint>

// Problem constants
#define B_  8
#define T_  4096
#define D_  1024
#define H_  16
#define DH_ 64
#define UMAX 48     // buffer rows per batch for Q-side (B*UMAX = 384 = hgemm M pad)
#define MP_ 768     // padded M rows per batch (>= H*u = 656), multiple of 128

// ---------------- scratch (device globals; zero-initialized) ----------------
__device__ __half g_Xsh[B_*UMAX*D_];           // gathered x rows, fp16 (pad rows stay 0)
__device__ float  g_Qs [B_*UMAX*D_];           // Q at idx (fp32, atomic target)
__device__ __half g_Qthi[(long)B_*MP_*D_];     // padded rows stay zero
__device__ __half g_Xhi [(long)B_*T_*D_];
__device__ __half g_S   [(long)B_*MP_*T_];     // scores (fp16)
__device__ __half g_Phi [(long)B_*MP_*T_];     // attn probs fp16 (padded rows zero)
__device__ float  g_AX  [(long)B_*MP_*D_];
__device__ float  g_ctx [B_*H_*UMAX*DH_];
__device__ float  g_mn  [B_*H_*DH_];
__device__ __half g_Yh  [B_*(UMAX+1)*D_];      // assembled rows fp16 (pad rows stay 0)
__device__ float  g_O   [B_*(UMAX+1)*D_];      // rows after Wo (atomic target)
__device__ __half g_Wqh [D_*D_];
__device__ __half g_Woh [D_*D_];

// ================= helpers =================
__device__ __forceinline__ uint32_t smem_u32(const void* p) {
    uint32_t a;
    asm("{ .reg .u64 t; cvta.to.shared.u64 t, %1; cvt.u32.u64 %0, t; }" : "=r"(a) : "l"(p));
    return a;
}
__device__ __forceinline__ void ldsm4(uint32_t& r0, uint32_t& r1, uint32_t& r2, uint32_t& r3,
                                      uint32_t a) {
    asm volatile("ldmatrix.sync.aligned.m8n8.x4.shared.b16 {%0,%1,%2,%3}, [%4];"
                 : "=r"(r0), "=r"(r1), "=r"(r2), "=r"(r3) : "r"(a));
}
__device__ __forceinline__ void ldsm4t(uint32_t& r0, uint32_t& r1, uint32_t& r2, uint32_t& r3,
                                       uint32_t a) {
    asm volatile("ldmatrix.sync.aligned.m8n8.x4.trans.shared.b16 {%0,%1,%2,%3}, [%4];"
                 : "=r"(r0), "=r"(r1), "=r"(r2), "=r"(r3) : "r"(a));
}
__device__ __forceinline__ void mma16816(float* d, const uint32_t* a, const uint32_t* b) {
    asm volatile("mma.sync.aligned.m16n8k16.row.col.f32.f16.f16.f32 "
                 "{%0,%1,%2,%3}, {%4,%5,%6,%7}, {%8,%9}, {%0,%1,%2,%3};"
                 : "+f"(d[0]), "+f"(d[1]), "+f"(d[2]), "+f"(d[3])
                 : "r"(a[0]), "r"(a[1]), "r"(a[2]), "r"(a[3]), "r"(b[0]), "r"(b[1]));
}
__device__ __forceinline__ void cp16(uint32_t s, const void* g) {
    asm volatile("cp.async.cg.shared.global [%0], [%1], 16;" :: "r"(s), "l"(g));
}
#define CP_COMMIT() asm volatile("cp.async.commit_group;" ::: "memory")
#define CP_WAIT(n)  asm volatile("cp.async.wait_group %0;" :: "n"(n) : "memory")

// ================= fp16 tensor-core GEMM (cp.async 3-stage, SW128) ==========
// NT: C[m,n] = sum_k A[m,k]*B[n,k]  (B row-major [N][K], ldb = K)
// NN: C[m,n] = sum_k A[m,k]*B[k,n]  (B row-major [K][N], ldb = ldbB)
// fp32 accum; C fp32 or fp16 (HALF_C). M,N mult of 128, (K/ZK) mult of 128.
// ZK>1: K-split with fp32 atomicAdd epilogue (C pre-zeroed); bias added at zk==0.
#define BK 64
#define TILE_B (128 * BK * 2)      // 16384 bytes per tile
#define HG_SMEM (3 * 2 * TILE_B)   // 98304 (3-stage)

template<bool NT, bool HALF_C>
__global__ void __launch_bounds__(256, 2)
hgemm(const __half* __restrict__ A, const __half* __restrict__ B,
      void* __restrict__ Cv, int K, int N, int ldbB, long sA, long sB, long sC,
      int ZK, const float* __restrict__ bias)
{
    extern __shared__ char dsm[];
    const uint32_t sb = smem_u32(dsm);
    const int tid = threadIdx.x, lane = tid & 31, wid = tid >> 5;
    const int zk = blockIdx.z % ZK;
    const int bz = blockIdx.z / ZK;
    const int m0 = blockIdx.y * 128, n0 = blockIdx.x * 128;
    const int wm = (wid & 3) * 32, wn = (wid >> 2) * 64;
    const int Kc = K / ZK, kbeg = zk * Kc;
    const __half* Ab = A + (long)bz * sA + (long)m0 * K + kbeg;
    const __half* Bb = NT ? (B + (long)bz * sB + (long)n0 * K + kbeg)
                          : (B + (long)bz * sB + (long)kbeg * ldbB + n0);

    float acc[2][8][4];
    #pragma unroll
    for (int i = 0; i < 2; i++)
        #pragma unroll
        for (int j = 0; j < 8; j++)
            #pragma unroll
            for (int q = 0; q < 4; q++) acc[i][j][q] = 0.f;

    const int fr = lane & 15, fc8 = lane >> 4;
    const int NCH = Kc / BK;

    auto issue = [&](int c) {
        const uint32_t base = sb + (uint32_t)(c % 3) * (2 * TILE_B);
        #pragma unroll
        for (int i = 0; i < 4; i++) {
            int idx = tid + i * 256;          // 0..1023
            int row = idx >> 3, cg = idx & 7;
            int phys = cg ^ (row & 7);
            cp16(base + (uint32_t)(row * 128 + phys * 16),
                 Ab + (long)row * K + c * BK + cg * 8);
        }
        if (NT) {
            #pragma unroll
            for (int i = 0; i < 4; i++) {
                int idx = tid + i * 256;
                int row = idx >> 3, cg = idx & 7;
                int phys = cg ^ (row & 7);
                cp16(base + TILE_B + (uint32_t)(row * 128 + phys * 16),
                     Bb + (long)row * K + c * BK + cg * 8);
            }
        } else {
            #pragma unroll
            for (int i = 0; i < 4; i++) {
                int idx = tid + i * 256;
                int row = idx >> 4, cg = idx & 15;
                int phys = cg ^ (row & 7);
                cp16(base + TILE_B + (uint32_t)(row * 256 + phys * 16),
                     Bb + (long)(c * BK + row) * ldbB + cg * 8);
            }
        }
    };

    issue(0); CP_COMMIT();
    issue(1); CP_COMMIT();
    for (int c = 0; c < NCH; c++) {
        CP_WAIT(1);
        __syncthreads();
        if (c + 2 < NCH) { issue(c + 2); CP_COMMIT(); }

        const uint32_t abase = sb + (uint32_t)(c % 3) * (2 * TILE_B);
        const uint32_t bbase = abase + TILE_B;
        #pragma unroll
        for (int kk = 0; kk < 4; kk++) {
            uint32_t a8[2][4], bh[8][2];
            #pragma unroll
            for (int mt = 0; mt < 2; mt++) {
                int row = wm + mt * 16 + fr;
                int cg = kk * 2 + fc8;
                int phys = cg ^ (row & 7);
                ldsm4(a8[mt][0], a8[mt][1], a8[mt][2], a8[mt][3],
                      abase + row * 128 + phys * 16);
            }
            #pragma unroll
            for (int p = 0; p < 4; p++) {
                uint32_t r0, r1, r2, r3;
                if (NT) {
                    int row = wn + p * 16 + fr;
                    int cg = kk * 2 + fc8;
                    int phys = cg ^ (row & 7);
                    ldsm4(r0, r1, r2, r3, bbase + row * 128 + phys * 16);
                } else {
                    int g = lane >> 3, j = lane & 7;
                    int krow = kk * 16 + ((g >> 1) << 3) + j;
                    int nchunk = ((wn + p * 16) >> 3) + (g & 1);
                    int phys = nchunk ^ (krow & 7);
                    ldsm4t(r0, r1, r2, r3, bbase + krow * 256 + phys * 16);
                }
                bh[2*p][0] = r0; bh[2*p+1][0] = r1; bh[2*p][1] = r2; bh[2*p+1][1] = r3;
            }
            #pragma unroll
            for (int mt = 0; mt < 2; mt++)
                #pragma unroll
                for (int nt = 0; nt < 8; nt++)
                    mma16816(acc[mt][nt], a8[mt], bh[nt]);
        }
    }

    const int qr = lane >> 2, qc = (lane & 3) * 2;
    #pragma unroll
    for (int mt = 0; mt < 2; mt++)
        #pragma unroll
        for (int nt = 0; nt < 8; nt++) {
            long r = m0 + wm + mt * 16 + qr;
            int cc = n0 + wn + nt * 8 + qc;
            if (HALF_C) {
                __half* Cb = (__half*)Cv + (long)bz * sC;
                *reinterpret_cast<__half2*>(&Cb[r * N + cc]) =
                    __floats2half2_rn(acc[mt][nt][0], acc[mt][nt][1]);
                *reinterpret_cast<__half2*>(&Cb[(r + 8) * N + cc]) =
                    __floats2half2_rn(acc[mt][nt][2], acc[mt][nt][3]);
            } else {
                float* Cb = (float*)Cv + (long)bz * sC;
                float v0 = acc[mt][nt][0], v1 = acc[mt][nt][1];
                float v2 = acc[mt][nt][2], v3 = acc[mt][nt][3];
                if (bias && zk == 0) {
                    v0 += bias[cc]; v1 += bias[cc + 1];
                    v2 += bias[cc]; v3 += bias[cc + 1];
                }
                if (ZK > 1) {
                    atomicAdd(&Cb[r * N + cc], v0);
                    atomicAdd(&Cb[r * N + cc + 1], v1);
                    atomicAdd(&Cb[(r + 8) * N + cc], v2);
                    atomicAdd(&Cb[(r + 8) * N + cc + 1], v3);
                } else {
                    *reinterpret_cast<float2*>(&Cb[r * N + cc]) = make_float2(v0, v1);
                    *reinterpret_cast<float2*>(&Cb[(r + 8) * N + cc]) = make_float2(v2, v3);
                }
            }
        }
}

// ================= batched 64x64-tile SIMT GEMM with K-split =================
template<bool NT, bool HALF_OUT>
__global__ void __launch_bounds__(256)
sgemm64(const float* __restrict__ A, const float* __restrict__ B, void* __restrict__ Cv,
        int M, int N, int K, int lda, int ldb, int ldc, int ZH, int ZK,
        long sAb, long sAh, long sBb, long sBh, long sCb, long sCh,
        const float* __restrict__ bias, float alpha)
{
    const int zk = blockIdx.z % ZK;
    const int zt = blockIdx.z / ZK;
    const int zb = zt / ZH, zh = zt % ZH;
    A += (long)zb * sAb + (long)zh * sAh;
    B += (long)zb * sBb + (long)zh * sBh;
    const long coff = (long)zb * sCb + (long)zh * sCh;

    __shared__ float As[16][68];
    __shared__ float Bs[16][68];

    const int m0 = blockIdx.y * 64, n0 = blockIdx.x * 64;
    const int tid = threadIdx.x;
    const int lr = tid >> 2;
    const int lk = (tid & 3) * 4;
    const int bk = tid >> 4;
    const int bn = (tid & 15) * 4;
    const int tm = (tid >> 4) * 4, tn = (tid & 15) * 4;

    float acc[4][4];
    #pragma unroll
    for (int i = 0; i < 4; i++)
        #pragma unroll
        for (int j = 0; j < 4; j++) acc[i][j] = 0.f;

    const int Kc = K / ZK;
    const int kbeg = zk * Kc, kend = kbeg + Kc;

    for (int k0 = kbeg; k0 < kend; k0 += 16) {
        {
            float4 v = make_float4(0.f, 0.f, 0.f, 0.f);
            int gm = m0 + lr;
            if (gm < M) v = *reinterpret_cast<const float4*>(A + (long)gm * lda + k0 + lk);
            As[lk + 0][lr] = v.x; As[lk + 1][lr] = v.y;
            As[lk + 2][lr] = v.z; As[lk + 3][lr] = v.w;
        }
        if (NT) {
            float4 v = *reinterpret_cast<const float4*>(B + (long)(n0 + lr) * ldb + k0 + lk);
            Bs[lk + 0][lr] = v.x; Bs[lk + 1][lr] = v.y;
            Bs[lk + 2][lr] = v.z; Bs[lk + 3][lr] = v.w;
        } else {
            float4 v = *reinterpret_cast<const float4*>(B + (long)(k0 + bk) * ldb + n0 + bn);
            *reinterpret_cast<float4*>(&Bs[bk][bn]) = v;
        }
        __syncthreads();

        #pragma unroll
        for (int kk = 0; kk < 16; kk++) {
            float ar[4], br[4];
            *reinterpret_cast<float4*>(ar) = *reinterpret_cast<const float4*>(&As[kk][tm]);
            *reinterpret_cast<float4*>(br) = *reinterpret_cast<const float4*>(&Bs[kk][tn]);
            #pragma unroll
            for (int i = 0; i < 4; i++)
                #pragma unroll
                for (int j = 0; j < 4; j++) acc[i][j] += ar[i] * br[j];
        }
        __syncthreads();
    }

    #pragma unroll
    for (int i = 0; i < 4; i++) {
        int gm = m0 + tm + i;
        if (gm >= M) break;
        #pragma unroll
        for (int j = 0; j < 4; j++) {
            int gn = n0 + tn + j;
            float v = acc[i][j] * alpha;
            if (bias && zk == 0) v += bias[gn];
            if (HALF_OUT) {
                ((__half*)Cv)[coff + (long)gm * ldc + gn] = __float2half_rn(v);
            } else if (ZK > 1) {
                atomicAdd(&((float*)Cv)[coff + (long)gm * ldc + gn], v);
            } else {
                ((float*)Cv)[coff + (long)gm * ldc + gn] = v;
            }
        }
    }
}

// ---------------- small kernels ----------------
__global__ void zero3_kernel(float4* __restrict__ a, long na,
                             float4* __restrict__ b, long nb,
                             float4* __restrict__ c, long nc)
{
    long i = (long)blockIdx.x * blockDim.x + threadIdx.x;
    float4 z = make_float4(0.f, 0.f, 0.f, 0.f);
    if (i < na) a[i] = z;
    if (i < nb) b[i] = z;
    if (i < nc) c[i] = z;
}

__global__ void conv_x_kernel(const float* __restrict__ x)
{
    long i = ((long)blockIdx.x * blockDim.x + threadIdx.x);
    long n4 = (long)B_ * T_ * D_ / 4;
    if (i >= n4) return;
    float4 v = reinterpret_cast<const float4*>(x)[i];
    __half h[4];
    h[0] = __float2half_rn(v.x); h[1] = __float2half_rn(v.y);
    h[2] = __float2half_rn(v.z); h[3] = __float2half_rn(v.w);
    *reinterpret_cast<uint2*>(&g_Xhi[i * 4]) = *reinterpret_cast<uint2*>(h);
}

// Wq, Wo -> fp16
__global__ void conv_w_kernel(const float* __restrict__ Wq, const float* __restrict__ Wo)
{
    long i = ((long)blockIdx.x * blockDim.x + threadIdx.x);
    long n4 = (long)D_ * D_ / 4;
    if (i >= n4) return;
    float4 a = reinterpret_cast<const float4*>(Wq)[i];
    float4 b = reinterpret_cast<const float4*>(Wo)[i];
    __half ha[4], hb[4];
    ha[0] = __float2half_rn(a.x); ha[1] = __float2half_rn(a.y);
    ha[2] = __float2half_rn(a.z); ha[3] = __float2half_rn(a.w);
    hb[0] = __float2half_rn(b.x); hb[1] = __float2half_rn(b.y);
    hb[2] = __float2half_rn(b.z); hb[3] = __float2half_rn(b.w);
    *reinterpret_cast<uint2*>(&g_Wqh[i * 4]) = *reinterpret_cast<uint2*>(ha);
    *reinterpret_cast<uint2*>(&g_Woh[i * 4]) = *reinterpret_cast<uint2*>(hb);
}

// gather x rows at idx -> fp16
__global__ void gather_kernel(const float* __restrict__ x, const int* __restrict__ idx, int u)
{
    int j = blockIdx.x, b = blockIdx.y;
    int t = idx[j];
    const float4* src = reinterpret_cast<const float4*>(x + ((long)b * T_ + t) * D_);
    __half* dst = g_Xsh + ((long)b * u + j) * D_;
    float4 v = src[threadIdx.x];
    __half h[4];
    h[0] = __float2half_rn(v.x); h[1] = __float2half_rn(v.y);
    h[2] = __float2half_rn(v.z); h[3] = __float2half_rn(v.w);
    *reinterpret_cast<uint2*>(&dst[threadIdx.x * 4]) = *reinterpret_cast<uint2*>(h);
}

// softmax over T (fp16 in/out), half2 vectorized, exp cached in registers
__global__ void softmax_kernel(int u)
{
    int MQ = H_ * u;
    int r = blockIdx.x % MQ, b = blockIdx.x / MQ;
    long row = (long)b * MP_ + r;
    const __half2* s2 = reinterpret_cast<const __half2*>(g_S + row * T_);
    __half2* p2 = reinterpret_cast<__half2*>(g_Phi + row * T_);
    int tid = threadIdx.x;   // 256
    __shared__ float red[256];
    const int NT2 = T_ / 2;          // 2048
    const int PER = NT2 / 256;       // 8 half2 per thread

    float2 v[PER];
    float mx = -1e30f;
    #pragma unroll
    for (int q = 0; q < PER; q++) {
        v[q] = __half22float2(s2[tid + q * 256]);
        mx = fmaxf(mx, fmaxf(v[q].x, v[q].y));
    }
    red[tid] = mx; __syncthreads();
    for (int o = 128; o > 0; o >>= 1) { if (tid < o) red[tid] = fmaxf(red[tid], red[tid + o]); __syncthreads(); }
    mx = red[0]; __syncthreads();

    float sum = 0.f;
    #pragma unroll
    for (int q = 0; q < PER; q++) {
        v[q].x = __expf(v[q].x - mx);
        v[q].y = __expf(v[q].y - mx);
        sum += v[q].x + v[q].y;
    }
    red[tid] = sum; __syncthreads();
    for (int o = 128; o > 0; o >>= 1) { if (tid < o) red[tid] += red[tid + o]; __syncthreads(); }
    float inv = 1.f / red[0];
    #pragma unroll
    for (int q = 0; q < PER; q++)
        p2[tid + q * 256] = __floats2half2_rn(v[q].x * inv, v[q].y * inv);
}

__global__ void mean_kernel(int u)
{
    int h = blockIdx.x, b = blockIdx.y;
    int e = threadIdx.x;   // 64
    float s = 0.f;
    const float* base = g_ctx + (long)(b * H_ + h) * u * DH_ + e;
    for (int j = 0; j < u; j++) s += base[(long)j * DH_];
    g_mn[(b * H_ + h) * DH_ + e] = s / (float)u;
}

// assemble Y rows (fp16): row 0 = mean, rows 1..u = ctx
__global__ void yrows_kernel(int u)
{
    int r = blockIdx.x, b = blockIdx.y;
    int tid = threadIdx.x;   // 256
    __half* out = g_Yh + ((long)b * (u + 1) + r) * D_;
    #pragma unroll
    for (int q = 0; q < 4; q++) {
        int d = tid * 4 + q;
        int h = d >> 6, e = d & 63;
        float v = (r == 0) ? g_mn[(b * H_ + h) * DH_ + e]
                           : g_ctx[((long)(b * H_ + h) * u + (r - 1)) * DH_ + e];
        out[d] = __float2half_rn(v);
    }
}

__global__ void bcast_kernel(float4* __restrict__ out, const float* __restrict__ O, int u)
{
    long i = (long)blockIdx.x * blockDim.x + threadIdx.x;
    long total = (long)B_ * T_ * (D_ / 4);
    if (i >= total) return;
    int d4 = (int)(i & 255);
    long bt = i >> 8;
    int b = (int)(bt >> 12);
    out[i] = reinterpret_cast<const float4*>(O + (long)b * (u + 1) * D_)[d4];
}

__global__ void scatter_kernel(float* __restrict__ out, const int* __restrict__ idx, int u)
{
    int j = blockIdx.x, b = blockIdx.y;
    int t = idx[j];
    const float4* src = reinterpret_cast<const float4*>(g_O + ((long)b * (u + 1) + 1 + j) * D_);
    float4* dst = reinterpret_cast<float4*>(out + ((long)b * T_ + t) * D_);
    dst[threadIdx.x] = src[threadIdx.x];
}

// ---------------- host launch ----------------
template<typename Tp>
static Tp* symaddr_t(const void* sym)
{
    void* p = nullptr;
    cudaGetSymbolAddress(&p, sym);
    return (Tp*)p;
}

extern "C" void kernel_launch(void* const* d_in, const int* in_sizes, int n_in,
                              void* d_out, int out_size)
{
    const float* x  = (const float*)d_in[0];
    const float* Wq = (const float*)d_in[1];
    const float* Wk = (const float*)d_in[2];
    const float* Wv = (const float*)d_in[3];
    const float* Wo = (const float*)d_in[4];
    const float* bo = (const float*)d_in[5];
    const int*  idx = (const int*)d_in[6];
    const int u = in_sizes[6];            // 41

    cudaFuncSetAttribute((const void*)hgemm<true, true>,
                         cudaFuncAttributeMaxDynamicSharedMemorySize, HG_SMEM);
    cudaFuncSetAttribute((const void*)hgemm<true, false>,
                         cudaFuncAttributeMaxDynamicSharedMemorySize, HG_SMEM);
    cudaFuncSetAttribute((const void*)hgemm<false, false>,
                         cudaFuncAttributeMaxDynamicSharedMemorySize, HG_SMEM);

    float* Qs = symaddr_t<float>(g_Qs);
    float* AX = symaddr_t<float>(g_AX);
    float* O  = symaddr_t<float>(g_O);
    float* CT = symaddr_t<float>(g_ctx);
    __half* Xsh  = symaddr_t<__half>(g_Xsh);
    __half* Qthi = symaddr_t<__half>(g_Qthi);
    __half* Xhi  = symaddr_t<__half>(g_Xhi);
    __half* S    = symaddr_t<__half>(g_S);
    __half* Phi  = symaddr_t<__half>(g_Phi);
    __half* Yh   = symaddr_t<__half>(g_Yh);
    __half* Wqh  = symaddr_t<__half>(g_Wqh);
    __half* Woh  = symaddr_t<__half>(g_Woh);

    const int MQ = H_ * u;                // 656
    const int KS = 8;                     // K-split for SIMT gemms
    const int KH = 4;                     // K-split for skinny hgemms

    // 0) zero atomic-accumulation targets (one launch)
    {
        long na = B_*UMAX*D_/4, nb = B_*H_*UMAX*DH_/4, nc = (long)B_*(UMAX+1)*D_/4;
        long nm = na > nb ? na : nb; if (nc > nm) nm = nc;
        zero3_kernel<<<(unsigned)((nm + 255)/256), 256>>>(
            (float4*)Qs, na, (float4*)CT, nb, (float4*)O, nc);
    }

    // 1) gather query rows (fp16); fp16 conversions of x and weights
    gather_kernel<<<dim3(u, B_), 256>>>(x, idx, u);
    {
        long n4 = (long)B_ * T_ * D_ / 4;
        conv_x_kernel<<<(unsigned)((n4 + 255) / 256), 256>>>(x);
    }
    conv_w_kernel<<<(D_ * D_ / 4 + 255) / 256, 256>>>(Wq, Wo);

    // 2) Qs = Xs @ Wq^T  (fp16 mma NT, fp32 atomic out: M=384, N=1024, K=1024, ZK=4)
    hgemm<true, false><<<dim3(D_ / 128, (B_ * UMAX) / 128, KH), 256, HG_SMEM>>>(
        Xsh, Wqh, Qs, D_, D_, 0, 0, 0, 0, KH, nullptr);

    // 3) Qt_h = scale * Qs_h @ Wk_h  (batched over (b,h): M=u, N=D, K=DH) -> fp16
    sgemm64<false, true><<<dim3(D_ / 64, 1, B_ * H_), 256>>>(
        Qs, Wk, Qthi, u, D_, DH_, D_, D_, D_, H_, 1,
        (long)u * D_, DH_, 0, (long)DH_ * D_, (long)MP_ * D_, (long)u * D_,
        nullptr, 0.125f);

    // 4) S[b] = Qt[b] @ x[b]^T  (fp16 mma NT, fp16 out: M=768, N=4096, K=1024)
    hgemm<true, true><<<dim3(T_ / 128, MP_ / 128, B_), 256, HG_SMEM>>>(
        Qthi, Xhi, S, D_, T_, 0,
        (long)MP_ * D_, (long)T_ * D_, (long)MP_ * T_, 1, nullptr);

    // 5) softmax (fp16 in) -> P fp16
    softmax_kernel<<<B_ * MQ, 256>>>(u);

    // 6) AX[b] = P[b] @ x[b]  (fp16 mma NN, fp32 out: M=768, N=1024, K=4096)
    hgemm<false, false><<<dim3(D_ / 128, MP_ / 128, B_), 256, HG_SMEM>>>(
        Phi, Xhi, AX, T_, D_, D_,
        (long)MP_ * T_, (long)T_ * D_, (long)MP_ * D_, 1, nullptr);

    // 7) ctx_h = AX_h @ Wv_h^T  (batched over (b,h): M=u, N=DH, K=D; K-split x8)
    sgemm64<true, false><<<dim3(1, 1, B_ * H_ * KS), 256>>>(
        AX, Wv, CT, u, DH_, D_, D_, D_, DH_, H_, KS,
        (long)MP_ * D_, (long)u * D_, 0, (long)DH_ * D_,
        (long)H_ * u * DH_, (long)u * DH_, nullptr, 1.f);

    // 8-9) mean, assemble rows (fp16)
    mean_kernel<<<dim3(H_, B_), 64>>>(u);
    yrows_kernel<<<dim3(u + 1, B_), 256>>>(u);

    // 10) O = Y @ Wo^T + bo  (fp16 mma NT, fp32 atomic out: M=384, N=1024, K=1024, ZK=4)
    hgemm<true, false><<<dim3(D_ / 128, (B_ * UMAX) / 128, KH), 256, HG_SMEM>>>(
        Yh, Woh, O, D_, D_, 0, 0, 0, 0, KH, bo);

    // 11-12) broadcast + scatter
    long total4 = (long)B_ * T_ * (D_ / 4);
    bcast_kernel<<<(unsigned)((total4 + 255) / 256), 256>>>((float4*)d_out, O, u);
    scatter_kernel<<<dim3(u, B_), 256>>>((float*)d_out, idx, u);
}